// round 5
// baseline (speedup 1.0000x reference)
#include <cuda_runtime.h>
#include <cuda_bf16.h>
#include <math.h>
#include <stdint.h>

// ---------------- problem constants ----------------
#define BN    2
#define SQL   1024
#define DIM   2048
#define NH    16
#define HD    128
#define SP    1024
#define SS    1024
#define SMm   512
#define SKV   2560
#define DP    1280
#define DS    1024
#define DMm   768
#define INNER 8192

typedef __nv_bfloat16 bf16;

// ---------------- scratch ----------------
__device__ __align__(256) float g_h  [BN*SQL*DIM];

__device__ __align__(256) bf16 g_xnh [BN*SQL*DIM];
__device__ __align__(256) bf16 g_xnl [BN*SQL*DIM];
__device__ __align__(256) bf16 g_pkh [BN*SP*DP];
__device__ __align__(256) bf16 g_pkl [BN*SP*DP];
__device__ __align__(256) bf16 g_skh [BN*SS*DS];
__device__ __align__(256) bf16 g_skl [BN*SS*DS];
__device__ __align__(256) bf16 g_mkh [BN*SMm*DMm];
__device__ __align__(256) bf16 g_mkl [BN*SMm*DMm];
__device__ __align__(256) bf16 g_cth [BN*SQL*DIM];
__device__ __align__(256) bf16 g_ctl [BN*SQL*DIM];
__device__ __align__(256) bf16 g_lnh [BN*SQL*DIM];
__device__ __align__(256) bf16 g_lnl [BN*SQL*DIM];
__device__ __align__(256) bf16 g_mdh [BN*SQL*INNER];
__device__ __align__(256) bf16 g_mdl [BN*SQL*INNER];

// q/k/v bf16 splits (q pre-scaled by 0.25); all row-major [S][DIM]
__device__ __align__(256) bf16 g_qh  [BN*SQL*DIM];
__device__ __align__(256) bf16 g_ql  [BN*SQL*DIM];
__device__ __align__(256) bf16 g_kh2 [BN*SKV*DIM];
__device__ __align__(256) bf16 g_kl2 [BN*SKV*DIM];
__device__ __align__(256) bf16 g_vh2 [BN*SKV*DIM];
__device__ __align__(256) bf16 g_vl2 [BN*SKV*DIM];

// transposed weight splits ([N][K] K-major)
__device__ __align__(256) bf16 g_wqh [DIM*DIM];
__device__ __align__(256) bf16 g_wql [DIM*DIM];
__device__ __align__(256) bf16 g_kph [DIM*DP];
__device__ __align__(256) bf16 g_kpl [DIM*DP];
__device__ __align__(256) bf16 g_vph [DIM*DP];
__device__ __align__(256) bf16 g_vpl [DIM*DP];
__device__ __align__(256) bf16 g_ksh [DIM*DS];
__device__ __align__(256) bf16 g_ksl [DIM*DS];
__device__ __align__(256) bf16 g_vsh [DIM*DS];
__device__ __align__(256) bf16 g_vsl [DIM*DS];
__device__ __align__(256) bf16 g_kmh [DIM*DMm];
__device__ __align__(256) bf16 g_kml [DIM*DMm];
__device__ __align__(256) bf16 g_vmh [DIM*DMm];
__device__ __align__(256) bf16 g_vml [DIM*DMm];
__device__ __align__(256) bf16 g_woh [DIM*DIM];
__device__ __align__(256) bf16 g_wol [DIM*DIM];
__device__ __align__(256) bf16 g_w1h [INNER*DIM];
__device__ __align__(256) bf16 g_w1l [INNER*DIM];
__device__ __align__(256) bf16 g_w2h [DIM*INNER];
__device__ __align__(256) bf16 g_w2l [DIM*INNER];

// ---------------- helpers ----------------
#define CP16(dst, src) asm volatile("cp.async.cg.shared.global [%0], [%1], 16;" :: "r"(dst), "l"(src))
#define CP4(dst, src)  asm volatile("cp.async.ca.shared.global [%0], [%1], 4;"  :: "r"(dst), "l"(src))
#define CP_COMMIT()  asm volatile("cp.async.commit_group;" ::: "memory")
#define CP_WAIT(n)   asm volatile("cp.async.wait_group %0;" :: "n"(n) : "memory")

__device__ __forceinline__ uint32_t smem_u32(const void* p) {
    uint32_t a;
    asm("{ .reg .u64 t; cvta.to.shared.u64 t, %1; cvt.u32.u64 %0, t; }" : "=r"(a) : "l"(p));
    return a;
}
__device__ __forceinline__ void mma_bf16(float* c, const uint32_t* a, const uint32_t* b) {
    asm volatile("mma.sync.aligned.m16n8k16.row.col.f32.bf16.bf16.f32 "
        "{%0,%1,%2,%3}, {%4,%5,%6,%7}, {%8,%9}, {%0,%1,%2,%3};"
        : "+f"(c[0]), "+f"(c[1]), "+f"(c[2]), "+f"(c[3])
        : "r"(a[0]), "r"(a[1]), "r"(a[2]), "r"(a[3]), "r"(b[0]), "r"(b[1]));
}
__device__ __forceinline__ void ldmx4(uint32_t* r, uint32_t addr) {
    asm volatile("ldmatrix.sync.aligned.m8n8.x4.shared.b16 {%0,%1,%2,%3}, [%4];"
        : "=r"(r[0]), "=r"(r[1]), "=r"(r[2]), "=r"(r[3]) : "r"(addr));
}
__device__ __forceinline__ void ldmx4t(uint32_t* r, uint32_t addr) {
    asm volatile("ldmatrix.sync.aligned.m8n8.x4.trans.shared.b16 {%0,%1,%2,%3}, [%4];"
        : "=r"(r[0]), "=r"(r[1]), "=r"(r[2]), "=r"(r[3]) : "r"(addr));
}
__device__ __forceinline__ void split2(float v, bf16& h, bf16& l) {
    h = __float2bfloat16(v);
    l = __float2bfloat16(v - __bfloat162float(h));
}
__device__ __forceinline__ uint32_t pack2(bf16 a, bf16 b) {
    __nv_bfloat162 t(a, b);
    return *(uint32_t*)&t;
}

// ---------------- split kernels ----------------
__global__ __launch_bounds__(256) void split_kernel(const float* __restrict__ x,
                                                    bf16* __restrict__ hi, bf16* __restrict__ lo, int n) {
    int i = blockIdx.x * 256 + threadIdx.x;
    if (i < n) { bf16 h, l; split2(x[i], h, l); hi[i] = h; lo[i] = l; }
}

__global__ __launch_bounds__(256) void tsplit_kernel(const float* __restrict__ W,
                                                     bf16* __restrict__ hi, bf16* __restrict__ lo,
                                                     int K, int N) {
    __shared__ float t[32][33];
    int n0 = blockIdx.x * 32, k0 = blockIdx.y * 32;
    int tx = threadIdx.x & 31, ty = threadIdx.x >> 5;
#pragma unroll
    for (int r = 0; r < 32; r += 8)
        t[ty + r][tx] = W[(size_t)(k0 + ty + r) * N + n0 + tx];
    __syncthreads();
#pragma unroll
    for (int r = 0; r < 32; r += 8) {
        float v = t[tx][ty + r];
        bf16 h, l; split2(v, h, l);
        size_t o = (size_t)(n0 + ty + r) * K + k0 + tx;
        hi[o] = h; lo[o] = l;
    }
}

__global__ __launch_bounds__(256) void rms_split_kernel(
    const float* __restrict__ x, const float* __restrict__ w,
    bf16* __restrict__ yh, bf16* __restrict__ yl) {
    __shared__ float red[256];
    int row = blockIdx.x;
    const float* xr = x + (size_t)row * DIM;
    float ss = 0.f;
    for (int c = threadIdx.x; c < DIM; c += 256) { float v = xr[c]; ss += v * v; }
    red[threadIdx.x] = ss; __syncthreads();
    for (int s = 128; s > 0; s >>= 1) {
        if (threadIdx.x < s) red[threadIdx.x] += red[threadIdx.x + s];
        __syncthreads();
    }
    float inv = rsqrtf(red[0] / (float)DIM + 1e-6f);
    for (int c = threadIdx.x; c < DIM; c += 256) {
        bf16 h, l; split2(xr[c] * inv * w[c], h, l);
        size_t o = (size_t)row * DIM + c;
        yh[o] = h; yl[o] = l;
    }
}

__global__ __launch_bounds__(256) void ln_split_kernel(
    const float* __restrict__ x, const float* __restrict__ g, const float* __restrict__ b,
    bf16* __restrict__ yh, bf16* __restrict__ yl) {
    __shared__ float r1[256], r2[256];
    int row = blockIdx.x;
    const float* xr = x + (size_t)row * DIM;
    float s1 = 0.f, s2 = 0.f;
    for (int c = threadIdx.x; c < DIM; c += 256) { float v = xr[c]; s1 += v; s2 += v * v; }
    r1[threadIdx.x] = s1; r2[threadIdx.x] = s2; __syncthreads();
    for (int s = 128; s > 0; s >>= 1) {
        if (threadIdx.x < s) { r1[threadIdx.x] += r1[threadIdx.x + s]; r2[threadIdx.x] += r2[threadIdx.x + s]; }
        __syncthreads();
    }
    float mu = r1[0] / (float)DIM;
    float rstd = rsqrtf(r2[0] / (float)DIM - mu * mu + 1e-5f);
    for (int c = threadIdx.x; c < DIM; c += 256) {
        bf16 h, l; split2((xr[c] - mu) * rstd * g[c] + b[c], h, l);
        size_t o = (size_t)row * DIM + c;
        yh[o] = h; yl[o] = l;
    }
}

// ---------------- mma.sync bf16x3 GEMM ----------------
// C[M,N] = A[M,K] @ B^T ; B stored [N][K]. Acc = Ahi*Bhi + Ahi*Blo + Alo*Bhi.
// epi: 0: C=acc+bias | 1: C=res+tanh(g)*(acc+bias) | 2: gelu->split | 3: C=res+tanh(g)*acc
//      4: (acc+bias)*scale -> split bf16 (row-major)
// Dual-output mode: when n0 >= nsplit, use B2/bias2/Chi2/Clo2 with n0 -= nsplit (merged K|V projection).
#define RS    40
#define ARRB  10240
#define STGB  40960

__global__ __launch_bounds__(256) void gemm_mma(
    const bf16* __restrict__ Ahi, const bf16* __restrict__ Alo, long aStride,
    const bf16* __restrict__ Bhi, const bf16* __restrict__ Blo,
    const bf16* __restrict__ Bhi2, const bf16* __restrict__ Blo2,
    const float* __restrict__ bias, const float* __restrict__ bias2,
    const float* __restrict__ res, const float* __restrict__ gate,
    float* __restrict__ C, bf16* __restrict__ Chi, bf16* __restrict__ Clo,
    bf16* __restrict__ Chi2, bf16* __restrict__ Clo2,
    long cStride, int M, int N, int K, float scale, int epi, int nsplit)
{
    extern __shared__ __align__(128) char dsm[];

    int tid = threadIdx.x, wid = tid >> 5, lid = tid & 31;
    int wm = wid & 3, wn = wid >> 2;
    int m0 = blockIdx.y << 7, n0 = blockIdx.x << 7;

    if (n0 >= nsplit) {
        Bhi = Bhi2; Blo = Blo2; bias = bias2;
        Chi = Chi2; Clo = Clo2;
        n0 -= nsplit;
    }

    Ahi += (size_t)blockIdx.z * aStride;
    Alo += (size_t)blockIdx.z * aStride;
    if (C) C += (size_t)blockIdx.z * cStride;
    if (Chi) { Chi += (size_t)blockIdx.z * cStride; Clo += (size_t)blockIdx.z * cStride; }

    uint32_t sbase = smem_u32(dsm);
    const bf16* aptr[4] = { Ahi + (size_t)m0 * K, Alo + (size_t)m0 * K,
                            Bhi + (size_t)n0 * K, Blo + (size_t)n0 * K };

    auto load_stage = [&](int k0, int st) {
        uint32_t base = sbase + (uint32_t)st * STGB;
#pragma unroll
        for (int arr = 0; arr < 4; arr++) {
            const bf16* p = aptr[arr];
            uint32_t ab = base + (uint32_t)arr * ARRB;
#pragma unroll
            for (int j = 0; j < 2; j++) {
                int rem = tid + j * 256;
                int row = rem >> 2, ch = rem & 3;
                CP16(ab + (uint32_t)(row * RS * 2 + ch * 16), p + (size_t)row * K + k0 + ch * 8);
            }
        }
    };

    float c[2][8][4];
#pragma unroll
    for (int mi = 0; mi < 2; mi++)
#pragma unroll
        for (int ni = 0; ni < 8; ni++)
#pragma unroll
            for (int r = 0; r < 4; r++) c[mi][ni][r] = 0.f;

    const int nt = K >> 5;
    load_stage(0, 0);
    CP_COMMIT();

    for (int t = 0; t < nt; t++) {
        int st = t & 1;
        if (t + 1 < nt) {
            load_stage((t + 1) << 5, st ^ 1);
            CP_COMMIT();
            CP_WAIT(1);
        } else {
            CP_WAIT(0);
        }
        __syncthreads();

        uint32_t Ah_b = sbase + (uint32_t)st * STGB;
        uint32_t Al_b = Ah_b + ARRB;
        uint32_t Bh_b = Ah_b + 2 * ARRB;
        uint32_t Bl_b = Ah_b + 3 * ARRB;

#pragma unroll
        for (int ks = 0; ks < 2; ks++) {
            int ko = ks * 16;
            uint32_t ah[2][4], al[2][4];
#pragma unroll
            for (int mi = 0; mi < 2; mi++) {
                uint32_t aoff = (uint32_t)((wm * 32 + mi * 16 + (lid & 15)) * RS + ko + ((lid >> 4) << 3)) * 2;
                ldmx4(ah[mi], Ah_b + aoff);
                ldmx4(al[mi], Al_b + aoff);
            }
#pragma unroll
            for (int nh2 = 0; nh2 < 2; nh2++) {
                uint32_t bh4[2][4], bl4[2][4];
#pragma unroll
                for (int p = 0; p < 2; p++) {
                    uint32_t brow = (uint32_t)(wn * 64 + nh2 * 32 + p * 16 + (lid & 7) + ((lid >> 4) << 3));
                    uint32_t boff = (brow * RS + ko + (((lid >> 3) & 1) << 3)) * 2;
                    ldmx4(bh4[p], Bh_b + boff);
                    ldmx4(bl4[p], Bl_b + boff);
                }
#pragma unroll
                for (int mi = 0; mi < 2; mi++)
#pragma unroll
                    for (int nj = 0; nj < 4; nj++) {
                        float* cc = c[mi][nh2 * 4 + nj];
                        const uint32_t* bh = &bh4[nj >> 1][(nj & 1) * 2];
                        const uint32_t* bl = &bl4[nj >> 1][(nj & 1) * 2];
                        mma_bf16(cc, ah[mi], bh);
                        mma_bf16(cc, ah[mi], bl);
                        mma_bf16(cc, al[mi], bh);
                    }
            }
        }
        __syncthreads();
    }

    float gv = (epi == 1 || epi == 3) ? tanhf(*gate) : 0.f;
#pragma unroll
    for (int mi = 0; mi < 2; mi++) {
#pragma unroll
        for (int ni = 0; ni < 8; ni++) {
            int col = n0 + wn * 64 + ni * 8 + (lid & 3) * 2;
            float bcol0 = 0.f, bcol1 = 0.f;
            if (epi == 0 || epi == 1 || epi == 4) { bcol0 = bias[col]; bcol1 = bias[col + 1]; }
#pragma unroll
            for (int rh = 0; rh < 2; rh++) {
                int m = m0 + wm * 32 + mi * 16 + (lid >> 2) + rh * 8;
                float v0 = c[mi][ni][rh * 2 + 0];
                float v1 = c[mi][ni][rh * 2 + 1];
                size_t o = (size_t)m * N + col;
                if (epi == 0) {
                    C[o] = v0 + bcol0; C[o + 1] = v1 + bcol1;
                } else if (epi == 1) {
                    C[o]     = res[o]     + gv * (v0 + bcol0);
                    C[o + 1] = res[o + 1] + gv * (v1 + bcol1);
                } else if (epi == 2) {
                    float g0 = 0.5f * v0 * (1.f + erff(v0 * 0.70710678118654752f));
                    float g1 = 0.5f * v1 * (1.f + erff(v1 * 0.70710678118654752f));
                    bf16 h0, l0, h1, l1;
                    split2(g0, h0, l0); split2(g1, h1, l1);
                    *(uint32_t*)&Chi[o] = pack2(h0, h1);
                    *(uint32_t*)&Clo[o] = pack2(l0, l1);
                } else if (epi == 3) {
                    C[o]     = res[o]     + gv * v0;
                    C[o + 1] = res[o + 1] + gv * v1;
                } else { // epi == 4
                    bf16 h0, l0, h1, l1;
                    split2((v0 + bcol0) * scale, h0, l0);
                    split2((v1 + bcol1) * scale, h1, l1);
                    *(uint32_t*)&Chi[o] = pack2(h0, h1);
                    *(uint32_t*)&Clo[o] = pack2(l0, l1);
                }
            }
        }
    }
}

// ---------------- tensor-core flash attention ----------------
// Br=128 (8 warps x 16 rows), Bc=64, HD=128. K and V both row-major [kv][d] in smem,
// V fragments loaded via ldmatrix.trans.
#define AQH 0
#define AQL 17408
#define AKH(st) (34816 + (st) * 17408)
#define AKL(st) (AKH(st) + 8704)
#define AVH(st) (69632 + (st) * 17408)
#define AVL(st) (AVH(st) + 8704)
#define AMSK_BYTES 208896
#define ATT_SMEM (AMSK_BYTES + 512)
#define NKT (SKV / 64)

__global__ __launch_bounds__(256) void attn_tc(
    const bf16* __restrict__ qh, const bf16* __restrict__ ql,
    const bf16* __restrict__ kh, const bf16* __restrict__ kl,
    const bf16* __restrict__ vh, const bf16* __restrict__ vl,
    const float* __restrict__ qmask, const float* __restrict__ pmask,
    const float* __restrict__ smask, const float* __restrict__ mmask,
    bf16* __restrict__ ch, bf16* __restrict__ cl)
{
    extern __shared__ __align__(128) char dsm[];
    uint32_t sb = smem_u32(dsm);

    int b = blockIdx.z, h = blockIdx.y, q0 = blockIdx.x * 128;
    int tid = threadIdx.x, wid = tid >> 5, lid = tid & 31;
    int wr = wid * 16;

    // Q prologue (hi+lo): 128 rows x 128 cols each
#pragma unroll
    for (int grp = 0; grp < 2; grp++) {
        const bf16* base = grp ? ql : qh;
        uint32_t ab = grp ? (uint32_t)AQL : (uint32_t)AQH;
#pragma unroll
        for (int j = 0; j < 8; j++) {
            int rem = tid + j * 256;
            int r = rem >> 4, cch = rem & 15;
            CP16(sb + (ab + (uint32_t)(r * 136 + cch * 8)) * 2,
                 base + (size_t)(b * SQL + q0 + r) * DIM + h * HD + cch * 8);
        }
    }

    auto load_stage = [&](int kt, int st) {
        const bf16* srcs[4] = { kh, kl, vh, vl };
        const uint32_t abase[4] = { (uint32_t)AKH(st), (uint32_t)AKL(st),
                                    (uint32_t)AVH(st), (uint32_t)AVL(st) };
#pragma unroll
        for (int grp = 0; grp < 4; grp++) {
            const bf16* base = srcs[grp];
            uint32_t ab = abase[grp];
#pragma unroll
            for (int j = 0; j < 4; j++) {
                int rem = tid + j * 256;
                int r = rem >> 4, cch = rem & 15;
                CP16(sb + (ab + (uint32_t)(r * 136 + cch * 8)) * 2,
                     base + (size_t)(b * SKV + kt + r) * DIM + h * HD + cch * 8);
            }
        }
        if (tid < 64) {
            int kidx = kt + tid;
            const float* srcm;
            if (kidx < SP)           srcm = pmask + b * SP + kidx;
            else if (kidx < SP + SS) srcm = smask + b * SS + (kidx - SP);
            else                     srcm = mmask + b * SMm + (kidx - SP - SS);
            CP4(sb + AMSK_BYTES + st * 256 + tid * 4, srcm);
        }
    };

    float qm2[2];
    qm2[0] = qmask[b * SQL + q0 + wr + (lid >> 2)];
    qm2[1] = qmask[b * SQL + q0 + wr + (lid >> 2) + 8];

    float m2[2] = { -1e30f, -1e30f }, l2[2] = { 0.f, 0.f };
    float o[16][4];
#pragma unroll
    for (int ni = 0; ni < 16; ni++)
#pragma unroll
        for (int r = 0; r < 4; r++) o[ni][r] = 0.f;

    load_stage(0, 0);
    CP_COMMIT();

    for (int t = 0; t < NKT; t++) {
        int st = t & 1;
        CP_WAIT(0);
        __syncthreads();
        if (t + 1 < NKT) { load_stage((t + 1) * 64, st ^ 1); CP_COMMIT(); }

        // ---- S = Qh*Kh + Qh*Kl + Ql*Kh ----
        float cs[8][4];
#pragma unroll
        for (int ni = 0; ni < 8; ni++)
#pragma unroll
            for (int r = 0; r < 4; r++) cs[ni][r] = 0.f;

        uint32_t akh = sb + (uint32_t)AKH(st) * 2;
        uint32_t akl = sb + (uint32_t)AKL(st) * 2;
#pragma unroll
        for (int ko = 0; ko < 8; ko++) {
            uint32_t aoff = (uint32_t)((wr + (lid & 15)) * 136 + ko * 16 + ((lid >> 4) << 3)) * 2;
            uint32_t aqh[4], aql[4];
            ldmx4(aqh, sb + AQH * 2 + aoff);
            ldmx4(aql, sb + (uint32_t)AQL * 2 + aoff);
#pragma unroll
            for (int p = 0; p < 4; p++) {
                uint32_t brow = (uint32_t)(p * 16 + (lid & 7) + ((lid >> 4) << 3));
                uint32_t boff = (brow * 136 + ko * 16 + (((lid >> 3) & 1) << 3)) * 2;
                uint32_t bh4[4], bl4[4];
                ldmx4(bh4, akh + boff);
                ldmx4(bl4, akl + boff);
#pragma unroll
                for (int half = 0; half < 2; half++) {
                    float* cc = cs[p * 2 + half];
                    mma_bf16(cc, aqh, &bh4[half * 2]);
                    mma_bf16(cc, aqh, &bl4[half * 2]);
                    mma_bf16(cc, aql, &bh4[half * 2]);
                }
            }
        }

        // ---- mask + online softmax ----
        const float* kmf = (const float*)(dsm + AMSK_BYTES + st * 256);
#pragma unroll
        for (int ni = 0; ni < 8; ni++) {
            int c0 = ni * 8 + (lid & 3) * 2;
            float km0 = kmf[c0], km1 = kmf[c0 + 1];
            if (qm2[0] == 0.f || km0 == 0.f) cs[ni][0] = -1e30f;
            if (qm2[0] == 0.f || km1 == 0.f) cs[ni][1] = -1e30f;
            if (qm2[1] == 0.f || km0 == 0.f) cs[ni][2] = -1e30f;
            if (qm2[1] == 0.f || km1 == 0.f) cs[ni][3] = -1e30f;
        }
#pragma unroll
        for (int rh = 0; rh < 2; rh++) {
            float mt = -1e30f;
#pragma unroll
            for (int ni = 0; ni < 8; ni++)
                mt = fmaxf(mt, fmaxf(cs[ni][rh * 2], cs[ni][rh * 2 + 1]));
            mt = fmaxf(mt, __shfl_xor_sync(0xffffffffu, mt, 1));
            mt = fmaxf(mt, __shfl_xor_sync(0xffffffffu, mt, 2));
            float nm = fmaxf(m2[rh], mt);
            float al = __expf(m2[rh] - nm);
            float ps = 0.f;
#pragma unroll
            for (int ni = 0; ni < 8; ni++) {
                float p0 = __expf(cs[ni][rh * 2] - nm);
                float p1 = __expf(cs[ni][rh * 2 + 1] - nm);
                cs[ni][rh * 2] = p0; cs[ni][rh * 2 + 1] = p1;
                ps += p0 + p1;
            }
            ps += __shfl_xor_sync(0xffffffffu, ps, 1);
            ps += __shfl_xor_sync(0xffffffffu, ps, 2);
            l2[rh] = l2[rh] * al + ps;
            m2[rh] = nm;
#pragma unroll
            for (int ni = 0; ni < 16; ni++) {
                o[ni][rh * 2] *= al; o[ni][rh * 2 + 1] *= al;
            }
        }

        // ---- PV: O += Ph*Vh + Ph*Vl + Pl*Vh (V row-major, trans ldmatrix) ----
        uint32_t avh = sb + (uint32_t)AVH(st) * 2;
        uint32_t avl = sb + (uint32_t)AVL(st) * 2;
#pragma unroll
        for (int kk = 0; kk < 4; kk++) {
            int t0 = 2 * kk, t1 = 2 * kk + 1;
            uint32_t pah[4], pal[4];
            {
                bf16 h00, l00, h01, l01, h10, l10, h11, l11;
                split2(cs[t0][0], h00, l00); split2(cs[t0][1], h01, l01);
                split2(cs[t0][2], h10, l10); split2(cs[t0][3], h11, l11);
                pah[0] = pack2(h00, h01); pal[0] = pack2(l00, l01);
                pah[1] = pack2(h10, h11); pal[1] = pack2(l10, l11);
                split2(cs[t1][0], h00, l00); split2(cs[t1][1], h01, l01);
                split2(cs[t1][2], h10, l10); split2(cs[t1][3], h11, l11);
                pah[2] = pack2(h00, h01); pal[2] = pack2(l00, l01);
                pah[3] = pack2(h10, h11); pal[3] = pack2(l10, l11);
            }
#pragma unroll
            for (int p = 0; p < 8; p++) {
                uint32_t kv = (uint32_t)(kk * 16 + ((lid >> 3) & 1) * 8 + (lid & 7));
                uint32_t d  = (uint32_t)(p * 16 + (((lid >> 4) & 1) << 3));
                uint32_t off = (kv * 136 + d) * 2;
                uint32_t bvh4[4], bvl4[4];
                ldmx4t(bvh4, avh + off);
                ldmx4t(bvl4, avl + off);
#pragma unroll
                for (int half = 0; half < 2; half++) {
                    float* oo = o[p * 2 + half];
                    mma_bf16(oo, pah, &bvh4[half * 2]);
                    mma_bf16(oo, pah, &bvl4[half * 2]);
                    mma_bf16(oo, pal, &bvh4[half * 2]);
                }
            }
        }
    }

    // ---- epilogue: o/l -> split bf16 ----
#pragma unroll
    for (int rh = 0; rh < 2; rh++) {
        float inv = 1.f / l2[rh];
        int row = q0 + wr + (lid >> 2) + rh * 8;
#pragma unroll
        for (int ni = 0; ni < 16; ni++) {
            int col = h * HD + ni * 8 + (lid & 3) * 2;
            size_t off = (size_t)(b * SQL + row) * DIM + col;
            bf16 h0, l0, h1, l1;
            split2(o[ni][rh * 2] * inv, h0, l0);
            split2(o[ni][rh * 2 + 1] * inv, h1, l1);
            *(uint32_t*)&ch[off] = pack2(h0, h1);
            *(uint32_t*)&cl[off] = pack2(l0, l1);
        }
    }
}

// ---------------- launch ----------------
extern "C" void kernel_launch(void* const* d_in, const int* in_sizes, int n_in,
                              void* d_out, int out_size)
{
    const float* x   = (const float*)d_in[0];
    const float* pkv = (const float*)d_in[1];
    const float* skv = (const float*)d_in[2];
    const float* mkv = (const float*)d_in[3];
    const float* qm  = (const float*)d_in[4];
    const float* pm  = (const float*)d_in[5];
    const float* smk = (const float*)d_in[6];
    const float* mmk = (const float*)d_in[7];
    const float* rw  = (const float*)d_in[8];
    const float* Wq  = (const float*)d_in[9];
    const float* bq  = (const float*)d_in[10];
    const float* Wkp = (const float*)d_in[11];
    const float* bkp = (const float*)d_in[12];
    const float* Wvp = (const float*)d_in[13];
    const float* bvp = (const float*)d_in[14];
    const float* Wks = (const float*)d_in[15];
    const float* bks = (const float*)d_in[16];
    const float* Wvs = (const float*)d_in[17];
    const float* bvs = (const float*)d_in[18];
    const float* Wkm = (const float*)d_in[19];
    const float* bkm = (const float*)d_in[20];
    const float* Wvm = (const float*)d_in[21];
    const float* bvm = (const float*)d_in[22];
    const float* Wo  = (const float*)d_in[23];
    const float* bo  = (const float*)d_in[24];
    const float* lg  = (const float*)d_in[25];
    const float* lb  = (const float*)d_in[26];
    const float* W1  = (const float*)d_in[27];
    const float* W2  = (const float*)d_in[28];
    const float* ga  = (const float*)d_in[29];
    const float* gf  = (const float*)d_in[30];
    float* out = (float*)d_out;

    float* hb;
    cudaGetSymbolAddress((void**)&hb, g_h);

    bf16 *xnh, *xnl, *pkh, *pkl, *skh, *skl, *mkh, *mkl, *cth, *ctl, *lnh, *lnl, *mdh, *mdl;
    cudaGetSymbolAddress((void**)&xnh, g_xnh); cudaGetSymbolAddress((void**)&xnl, g_xnl);
    cudaGetSymbolAddress((void**)&pkh, g_pkh); cudaGetSymbolAddress((void**)&pkl, g_pkl);
    cudaGetSymbolAddress((void**)&skh, g_skh); cudaGetSymbolAddress((void**)&skl, g_skl);
    cudaGetSymbolAddress((void**)&mkh, g_mkh); cudaGetSymbolAddress((void**)&mkl, g_mkl);
    cudaGetSymbolAddress((void**)&cth, g_cth); cudaGetSymbolAddress((void**)&ctl, g_ctl);
    cudaGetSymbolAddress((void**)&lnh, g_lnh); cudaGetSymbolAddress((void**)&lnl, g_lnl);
    cudaGetSymbolAddress((void**)&mdh, g_mdh); cudaGetSymbolAddress((void**)&mdl, g_mdl);

    bf16 *qh, *ql, *kh, *kl, *vh, *vl;
    cudaGetSymbolAddress((void**)&qh, g_qh);  cudaGetSymbolAddress((void**)&ql, g_ql);
    cudaGetSymbolAddress((void**)&kh, g_kh2); cudaGetSymbolAddress((void**)&kl, g_kl2);
    cudaGetSymbolAddress((void**)&vh, g_vh2); cudaGetSymbolAddress((void**)&vl, g_vl2);

    bf16 *wqh, *wql, *kph, *kpl, *vph, *vpl, *ksh, *ksl, *vsh, *vsl, *kmh, *kml, *vmh, *vml, *woh, *wol, *w1h, *w1l, *w2h, *w2l;
    cudaGetSymbolAddress((void**)&wqh, g_wqh); cudaGetSymbolAddress((void**)&wql, g_wql);
    cudaGetSymbolAddress((void**)&kph, g_kph); cudaGetSymbolAddress((void**)&kpl, g_kpl);
    cudaGetSymbolAddress((void**)&vph, g_vph); cudaGetSymbolAddress((void**)&vpl, g_vpl);
    cudaGetSymbolAddress((void**)&ksh, g_ksh); cudaGetSymbolAddress((void**)&ksl, g_ksl);
    cudaGetSymbolAddress((void**)&vsh, g_vsh); cudaGetSymbolAddress((void**)&vsl, g_vsl);
    cudaGetSymbolAddress((void**)&kmh, g_kmh); cudaGetSymbolAddress((void**)&kml, g_kml);
    cudaGetSymbolAddress((void**)&vmh, g_vmh); cudaGetSymbolAddress((void**)&vml, g_vml);
    cudaGetSymbolAddress((void**)&woh, g_woh); cudaGetSymbolAddress((void**)&wol, g_wol);
    cudaGetSymbolAddress((void**)&w1h, g_w1h); cudaGetSymbolAddress((void**)&w1l, g_w1l);
    cudaGetSymbolAddress((void**)&w2h, g_w2h); cudaGetSymbolAddress((void**)&w2l, g_w2l);

    size_t gemm_sh = 2 * STGB;
    cudaFuncSetAttribute(gemm_mma, cudaFuncAttributeMaxDynamicSharedMemorySize, (int)gemm_sh);
    cudaFuncSetAttribute(attn_tc, cudaFuncAttributeMaxDynamicSharedMemorySize, ATT_SMEM);

    const int NS = 1 << 30;   // nsplit sentinel: never switch

    // 1) weight transpose + split
    tsplit_kernel<<<dim3(DIM / 32, DIM / 32),  256>>>(Wq,  wqh, wql, DIM,   DIM);
    tsplit_kernel<<<dim3(DIM / 32, DP / 32),   256>>>(Wkp, kph, kpl, DP,    DIM);
    tsplit_kernel<<<dim3(DIM / 32, DP / 32),   256>>>(Wvp, vph, vpl, DP,    DIM);
    tsplit_kernel<<<dim3(DIM / 32, DS / 32),   256>>>(Wks, ksh, ksl, DS,    DIM);
    tsplit_kernel<<<dim3(DIM / 32, DS / 32),   256>>>(Wvs, vsh, vsl, DS,    DIM);
    tsplit_kernel<<<dim3(DIM / 32, DMm / 32),  256>>>(Wkm, kmh, kml, DMm,   DIM);
    tsplit_kernel<<<dim3(DIM / 32, DMm / 32),  256>>>(Wvm, vmh, vml, DMm,   DIM);
    tsplit_kernel<<<dim3(DIM / 32, DIM / 32),  256>>>(Wo,  woh, wol, DIM,   DIM);
    tsplit_kernel<<<dim3(INNER / 32, DIM / 32), 256>>>(W1, w1h, w1l, DIM,   INNER);
    tsplit_kernel<<<dim3(DIM / 32, INNER / 32), 256>>>(W2, w2h, w2l, INNER, DIM);

    // 2) activation splits
    rms_split_kernel<<<BN * SQL, 256>>>(x, rw, xnh, xnl);
    split_kernel<<<(BN * SP * DP) / 256,   256>>>(pkv, pkh, pkl, BN * SP * DP);
    split_kernel<<<(BN * SS * DS) / 256,   256>>>(skv, skh, skl, BN * SS * DS);
    split_kernel<<<(BN * SMm * DMm) / 256, 256>>>(mkv, mkh, mkl, BN * SMm * DMm);

    // 3) Q projection (scaled 0.25 -> split)
    gemm_mma<<<dim3(DIM / 128, 16, 1), 256, gemm_sh>>>(
        xnh, xnl, 0, wqh, wql, wqh, wql, bq, bq, nullptr, nullptr,
        nullptr, qh, ql, qh, ql, 0, BN * SQL, DIM, DIM, 0.25f, 4, NS);

    // 3b) merged K|V projections per segment (N-split at DIM)
    gemm_mma<<<dim3(2 * DIM / 128, SP / 128, BN), 256, gemm_sh>>>(
        pkh, pkl, (long)SP * DP, kph, kpl, vph, vpl, bkp, bvp, nullptr, nullptr,
        nullptr, kh, kl, vh, vl, (long)SKV * DIM, SP, DIM, DP, 1.f, 4, DIM);
    gemm_mma<<<dim3(2 * DIM / 128, SS / 128, BN), 256, gemm_sh>>>(
        skh, skl, (long)SS * DS, ksh, ksl, vsh, vsl, bks, bvs, nullptr, nullptr,
        nullptr, kh + (size_t)SP * DIM, kl + (size_t)SP * DIM,
        vh + (size_t)SP * DIM, vl + (size_t)SP * DIM, (long)SKV * DIM, SS, DIM, DS, 1.f, 4, DIM);
    gemm_mma<<<dim3(2 * DIM / 128, SMm / 128, BN), 256, gemm_sh>>>(
        mkh, mkl, (long)SMm * DMm, kmh, kml, vmh, vml, bkm, bvm, nullptr, nullptr,
        nullptr, kh + (size_t)(SP + SS) * DIM, kl + (size_t)(SP + SS) * DIM,
        vh + (size_t)(SP + SS) * DIM, vl + (size_t)(SP + SS) * DIM, (long)SKV * DIM, SMm, DIM, DMm, 1.f, 4, DIM);

    // 4) tensor-core flash attention -> ctx split
    attn_tc<<<dim3(SQL / 128, NH, BN), 256, ATT_SMEM>>>(qh, ql, kh, kl, vh, vl,
                                                        qm, pm, smk, mmk, cth, ctl);

    // 5) Wo projection + gated residual
    gemm_mma<<<dim3(DIM / 128, 16, 1), 256, gemm_sh>>>(
        cth, ctl, 0, woh, wol, woh, wol, bo, bo, x, ga,
        hb, nullptr, nullptr, nullptr, nullptr, 0, BN * SQL, DIM, DIM, 1.f, 1, NS);

    // 6) LayerNorm -> split
    ln_split_kernel<<<BN * SQL, 256>>>(hb, lg, lb, lnh, lnl);

    // 7) FFW up + GELU -> split
    gemm_mma<<<dim3(INNER / 128, 16, 1), 256, gemm_sh>>>(
        lnh, lnl, 0, w1h, w1l, w1h, w1l, nullptr, nullptr, nullptr, nullptr,
        nullptr, mdh, mdl, mdh, mdl, 0, BN * SQL, INNER, DIM, 1.f, 2, NS);

    // 8) FFW down + gated residual -> out
    gemm_mma<<<dim3(DIM / 128, 16, 1), 256, gemm_sh>>>(
        mdh, mdl, 0, w2h, w2l, w2h, w2l, nullptr, nullptr, hb, gf,
        out, nullptr, nullptr, nullptr, nullptr, 0, BN * SQL, DIM, INNER, 1.f, 3, NS);
}

// round 7
// speedup vs baseline: 1.3827x; 1.3827x over previous
#include <cuda_runtime.h>
#include <cuda_fp16.h>
#include <math.h>
#include <stdint.h>

// ---------------- problem constants ----------------
#define BN    2
#define SQL   1024
#define DIM   2048
#define NH    16
#define HD    128
#define SP    1024
#define SS    1024
#define SMm   512
#define SKV   2560
#define DP    1280
#define DS    1024
#define DMm   768
#define INNER 8192

typedef __half fp16;

// ---------------- scratch ----------------
__device__ __align__(256) float g_h  [BN*SQL*DIM];

// activation splits (A-side: hi/lo fp16)
__device__ __align__(256) fp16 g_xnh [BN*SQL*DIM];
__device__ __align__(256) fp16 g_xnl [BN*SQL*DIM];
__device__ __align__(256) fp16 g_pkh [BN*SP*DP];
__device__ __align__(256) fp16 g_pkl [BN*SP*DP];
__device__ __align__(256) fp16 g_skh [BN*SS*DS];
__device__ __align__(256) fp16 g_skl [BN*SS*DS];
__device__ __align__(256) fp16 g_mkh [BN*SMm*DMm];
__device__ __align__(256) fp16 g_mkl [BN*SMm*DMm];
__device__ __align__(256) fp16 g_cth [BN*SQL*DIM];
__device__ __align__(256) fp16 g_ctl [BN*SQL*DIM];
__device__ __align__(256) fp16 g_lnh [BN*SQL*DIM];
__device__ __align__(256) fp16 g_lnl [BN*SQL*DIM];
__device__ __align__(256) fp16 g_mdh [BN*SQL*INNER];
__device__ __align__(256) fp16 g_mdl [BN*SQL*INNER];

// q hi/lo (pre-scaled 0.25); k/v single fp16, row-major [S][DIM]
__device__ __align__(256) fp16 g_qh  [BN*SQL*DIM];
__device__ __align__(256) fp16 g_ql  [BN*SQL*DIM];
__device__ __align__(256) fp16 g_k1  [BN*SKV*DIM];
__device__ __align__(256) fp16 g_v1  [BN*SKV*DIM];

// transposed single-fp16 weights ([N][K] K-major)
__device__ __align__(256) fp16 g_wq [DIM*DIM];
__device__ __align__(256) fp16 g_kp [DIM*DP];
__device__ __align__(256) fp16 g_vp [DIM*DP];
__device__ __align__(256) fp16 g_ks [DIM*DS];
__device__ __align__(256) fp16 g_vs [DIM*DS];
__device__ __align__(256) fp16 g_km [DIM*DMm];
__device__ __align__(256) fp16 g_vm [DIM*DMm];
__device__ __align__(256) fp16 g_wo [DIM*DIM];
__device__ __align__(256) fp16 g_w1 [INNER*DIM];
__device__ __align__(256) fp16 g_w2 [DIM*INNER];

// ---------------- helpers ----------------
#define CP16(dst, src) asm volatile("cp.async.cg.shared.global [%0], [%1], 16;" :: "r"(dst), "l"(src))
#define CP4(dst, src)  asm volatile("cp.async.ca.shared.global [%0], [%1], 4;"  :: "r"(dst), "l"(src))
#define CP_COMMIT()  asm volatile("cp.async.commit_group;" ::: "memory")
#define CP_WAIT(n)   asm volatile("cp.async.wait_group %0;" :: "n"(n) : "memory")

__device__ __forceinline__ uint32_t smem_u32(const void* p) {
    uint32_t a;
    asm("{ .reg .u64 t; cvta.to.shared.u64 t, %1; cvt.u32.u64 %0, t; }" : "=r"(a) : "l"(p));
    return a;
}
__device__ __forceinline__ void mma_f16(float* c, const uint32_t* a, const uint32_t* b) {
    asm volatile("mma.sync.aligned.m16n8k16.row.col.f32.f16.f16.f32 "
        "{%0,%1,%2,%3}, {%4,%5,%6,%7}, {%8,%9}, {%0,%1,%2,%3};"
        : "+f"(c[0]), "+f"(c[1]), "+f"(c[2]), "+f"(c[3])
        : "r"(a[0]), "r"(a[1]), "r"(a[2]), "r"(a[3]), "r"(b[0]), "r"(b[1]));
}
__device__ __forceinline__ void ldmx4(uint32_t* r, uint32_t addr) {
    asm volatile("ldmatrix.sync.aligned.m8n8.x4.shared.b16 {%0,%1,%2,%3}, [%4];"
        : "=r"(r[0]), "=r"(r[1]), "=r"(r[2]), "=r"(r[3]) : "r"(addr));
}
__device__ __forceinline__ void ldmx4t(uint32_t* r, uint32_t addr) {
    asm volatile("ldmatrix.sync.aligned.m8n8.x4.trans.shared.b16 {%0,%1,%2,%3}, [%4];"
        : "=r"(r[0]), "=r"(r[1]), "=r"(r[2]), "=r"(r[3]) : "r"(addr));
}
__device__ __forceinline__ void split2(float v, fp16& h, fp16& l) {
    h = __float2half_rn(v);
    l = __float2half_rn(v - __half2float(h));
}
__device__ __forceinline__ uint32_t pack2(fp16 a, fp16 b) {
    __half2 t(a, b);
    return *(uint32_t*)&t;
}

// ---------------- prep kernels ----------------
__global__ __launch_bounds__(256) void split_kernel(const float* __restrict__ x,
                                                    fp16* __restrict__ hi, fp16* __restrict__ lo, int n) {
    int i = blockIdx.x * 256 + threadIdx.x;
    if (i < n) { fp16 h, l; split2(x[i], h, l); hi[i] = h; lo[i] = l; }
}

// transpose to single fp16: W[K][N] -> [N][K]
__global__ __launch_bounds__(256) void tsplit_kernel(const float* __restrict__ W,
                                                     fp16* __restrict__ outw, int K, int N) {
    __shared__ float t[32][33];
    int n0 = blockIdx.x * 32, k0 = blockIdx.y * 32;
    int tx = threadIdx.x & 31, ty = threadIdx.x >> 5;
#pragma unroll
    for (int r = 0; r < 32; r += 8)
        t[ty + r][tx] = W[(size_t)(k0 + ty + r) * N + n0 + tx];
    __syncthreads();
#pragma unroll
    for (int r = 0; r < 32; r += 8)
        outw[(size_t)(n0 + ty + r) * K + k0 + tx] = __float2half_rn(t[tx][ty + r]);
}

__global__ __launch_bounds__(256) void rms_split_kernel(
    const float* __restrict__ x, const float* __restrict__ w,
    fp16* __restrict__ yh, fp16* __restrict__ yl) {
    __shared__ float red[256];
    int row = blockIdx.x;
    const float* xr = x + (size_t)row * DIM;
    float ss = 0.f;
    for (int c = threadIdx.x; c < DIM; c += 256) { float v = xr[c]; ss += v * v; }
    red[threadIdx.x] = ss; __syncthreads();
    for (int s = 128; s > 0; s >>= 1) {
        if (threadIdx.x < s) red[threadIdx.x] += red[threadIdx.x + s];
        __syncthreads();
    }
    float inv = rsqrtf(red[0] / (float)DIM + 1e-6f);
    for (int c = threadIdx.x; c < DIM; c += 256) {
        fp16 h, l; split2(xr[c] * inv * w[c], h, l);
        size_t o = (size_t)row * DIM + c;
        yh[o] = h; yl[o] = l;
    }
}

__global__ __launch_bounds__(256) void ln_split_kernel(
    const float* __restrict__ x, const float* __restrict__ g, const float* __restrict__ b,
    fp16* __restrict__ yh, fp16* __restrict__ yl) {
    __shared__ float r1[256], r2[256];
    int row = blockIdx.x;
    const float* xr = x + (size_t)row * DIM;
    float s1 = 0.f, s2 = 0.f;
    for (int c = threadIdx.x; c < DIM; c += 256) { float v = xr[c]; s1 += v; s2 += v * v; }
    r1[threadIdx.x] = s1; r2[threadIdx.x] = s2; __syncthreads();
    for (int s = 128; s > 0; s >>= 1) {
        if (threadIdx.x < s) { r1[threadIdx.x] += r1[threadIdx.x + s]; r2[threadIdx.x] += r2[threadIdx.x + s]; }
        __syncthreads();
    }
    float mu = r1[0] / (float)DIM;
    float rstd = rsqrtf(r2[0] / (float)DIM - mu * mu + 1e-5f);
    for (int c = threadIdx.x; c < DIM; c += 256) {
        fp16 h, l; split2((xr[c] - mu) * rstd * g[c] + b[c], h, l);
        size_t o = (size_t)row * DIM + c;
        yh[o] = h; yl[o] = l;
    }
}

// ---------------- mma.sync fp16 2-term GEMM ----------------
// C[M,N] = A[M,K] @ B^T ; B stored [N][K] single fp16. Acc = Ahi*B + Alo*B.
// epi: 0: C=acc+bias (f32) | 1: C=res+tanh(g)*(acc+bias) | 2: gelu->split | 3: C=res+tanh(g)*acc
//      4: (acc+bias)*scale -> split fp16 | 6: acc+bias -> single fp16 (Oh only)
// Dual-output: when n0 >= nsplit, use B2/bias2/Oh2/Ol2 with n0 -= nsplit.
#define RS    40
#define ARRB  10240
#define STGB  30720

__global__ __launch_bounds__(256) void gemm_mma(
    const fp16* __restrict__ Ahi, const fp16* __restrict__ Alo, long aStride,
    const fp16* __restrict__ B, const fp16* __restrict__ B2,
    const float* __restrict__ bias, const float* __restrict__ bias2,
    const float* __restrict__ res, const float* __restrict__ gate,
    float* __restrict__ C, fp16* __restrict__ Oh, fp16* __restrict__ Ol,
    fp16* __restrict__ Oh2, fp16* __restrict__ Ol2,
    long cStride, int M, int N, int K, float scale, int epi, int nsplit)
{
    extern __shared__ __align__(128) char dsm[];

    int tid = threadIdx.x, wid = tid >> 5, lid = tid & 31;
    int wm = wid & 3, wn = wid >> 2;
    int m0 = blockIdx.y << 7, n0 = blockIdx.x << 7;

    if (n0 >= nsplit) {
        B = B2; bias = bias2; Oh = Oh2; Ol = Ol2;
        n0 -= nsplit;
    }

    Ahi += (size_t)blockIdx.z * aStride;
    Alo += (size_t)blockIdx.z * aStride;
    if (C)  C  += (size_t)blockIdx.z * cStride;
    if (Oh) Oh += (size_t)blockIdx.z * cStride;
    if (Ol) Ol += (size_t)blockIdx.z * cStride;

    uint32_t sbase = smem_u32(dsm);
    const fp16* aptr[3] = { Ahi + (size_t)m0 * K, Alo + (size_t)m0 * K, B + (size_t)n0 * K };

    auto load_stage = [&](int k0, int st) {
        uint32_t base = sbase + (uint32_t)st * STGB;
#pragma unroll
        for (int arr = 0; arr < 3; arr++) {
            const fp16* p = aptr[arr];
            uint32_t ab = base + (uint32_t)arr * ARRB;
#pragma unroll
            for (int j = 0; j < 2; j++) {
                int rem = tid + j * 256;
                int row = rem >> 2, ch = rem & 3;
                CP16(ab + (uint32_t)(row * RS * 2 + ch * 16), p + (size_t)row * K + k0 + ch * 8);
            }
        }
    };

    float c[2][8][4];
#pragma unroll
    for (int mi = 0; mi < 2; mi++)
#pragma unroll
        for (int ni = 0; ni < 8; ni++)
#pragma unroll
            for (int r = 0; r < 4; r++) c[mi][ni][r] = 0.f;

    const int nt = K >> 5;
    load_stage(0, 0);
    CP_COMMIT();

    for (int t = 0; t < nt; t++) {
        int st = t & 1;
        if (t + 1 < nt) {
            load_stage((t + 1) << 5, st ^ 1);
            CP_COMMIT();
            CP_WAIT(1);
        } else {
            CP_WAIT(0);
        }
        __syncthreads();

        uint32_t Ah_b = sbase + (uint32_t)st * STGB;
        uint32_t Al_b = Ah_b + ARRB;
        uint32_t B_b  = Ah_b + 2 * ARRB;

#pragma unroll
        for (int ks = 0; ks < 2; ks++) {
            int ko = ks * 16;
            uint32_t ah[2][4], al[2][4];
#pragma unroll
            for (int mi = 0; mi < 2; mi++) {
                uint32_t aoff = (uint32_t)((wm * 32 + mi * 16 + (lid & 15)) * RS + ko + ((lid >> 4) << 3)) * 2;
                ldmx4(ah[mi], Ah_b + aoff);
                ldmx4(al[mi], Al_b + aoff);
            }
#pragma unroll
            for (int nh2 = 0; nh2 < 2; nh2++) {
                uint32_t b4[2][4];
#pragma unroll
                for (int p = 0; p < 2; p++) {
                    uint32_t brow = (uint32_t)(wn * 64 + nh2 * 32 + p * 16 + (lid & 7) + ((lid >> 4) << 3));
                    uint32_t boff = (brow * RS + ko + (((lid >> 3) & 1) << 3)) * 2;
                    ldmx4(b4[p], B_b + boff);
                }
#pragma unroll
                for (int mi = 0; mi < 2; mi++)
#pragma unroll
                    for (int nj = 0; nj < 4; nj++) {
                        float* cc = c[mi][nh2 * 4 + nj];
                        const uint32_t* bb = &b4[nj >> 1][(nj & 1) * 2];
                        mma_f16(cc, ah[mi], bb);
                        mma_f16(cc, al[mi], bb);
                    }
            }
        }
        __syncthreads();
    }

    float gv = (epi == 1 || epi == 3) ? tanhf(*gate) : 0.f;
#pragma unroll
    for (int mi = 0; mi < 2; mi++) {
#pragma unroll
        for (int ni = 0; ni < 8; ni++) {
            int col = n0 + wn * 64 + ni * 8 + (lid & 3) * 2;
            float bcol0 = 0.f, bcol1 = 0.f;
            if (epi != 2 && epi != 3) { bcol0 = bias[col]; bcol1 = bias[col + 1]; }
#pragma unroll
            for (int rh = 0; rh < 2; rh++) {
                int m = m0 + wm * 32 + mi * 16 + (lid >> 2) + rh * 8;
                float v0 = c[mi][ni][rh * 2 + 0];
                float v1 = c[mi][ni][rh * 2 + 1];
                size_t o = (size_t)m * N + col;
                if (epi == 0) {
                    C[o] = v0 + bcol0; C[o + 1] = v1 + bcol1;
                } else if (epi == 1) {
                    C[o]     = res[o]     + gv * (v0 + bcol0);
                    C[o + 1] = res[o + 1] + gv * (v1 + bcol1);
                } else if (epi == 2) {
                    float g0 = 0.5f * v0 * (1.f + erff(v0 * 0.70710678118654752f));
                    float g1 = 0.5f * v1 * (1.f + erff(v1 * 0.70710678118654752f));
                    fp16 h0, l0, h1, l1;
                    split2(g0, h0, l0); split2(g1, h1, l1);
                    *(uint32_t*)&Oh[o] = pack2(h0, h1);
                    *(uint32_t*)&Ol[o] = pack2(l0, l1);
                } else if (epi == 3) {
                    C[o]     = res[o]     + gv * v0;
                    C[o + 1] = res[o + 1] + gv * v1;
                } else if (epi == 4) {
                    fp16 h0, l0, h1, l1;
                    split2((v0 + bcol0) * scale, h0, l0);
                    split2((v1 + bcol1) * scale, h1, l1);
                    *(uint32_t*)&Oh[o] = pack2(h0, h1);
                    *(uint32_t*)&Ol[o] = pack2(l0, l1);
                } else { // epi == 6: single fp16
                    *(uint32_t*)&Oh[o] = pack2(__float2half_rn(v0 + bcol0), __float2half_rn(v1 + bcol1));
                }
            }
        }
    }
}

// ---------------- tensor-core flash attention ----------------
// Br=128 (8 warps x 16 rows), Bc=64, HD=128. Q hi/lo; K,V single fp16 row-major.
// QK: qh*K + ql*K. PV: Ph*V + Pl*V (V via ldmatrix.trans).
#define AQH 0
#define AQL 17408
#define AK(st) (34816 + (st) * 8704)
#define AV(st) (52224 + (st) * 8704)
#define AMSK_BYTES 139264
#define ATT_SMEM (AMSK_BYTES + 512)
#define NKT (SKV / 64)

__global__ __launch_bounds__(256) void attn_tc(
    const fp16* __restrict__ qh, const fp16* __restrict__ ql,
    const fp16* __restrict__ kk, const fp16* __restrict__ vv,
    const float* __restrict__ qmask, const float* __restrict__ pmask,
    const float* __restrict__ smask, const float* __restrict__ mmask,
    fp16* __restrict__ ch, fp16* __restrict__ cl)
{
    extern __shared__ __align__(128) char dsm[];
    uint32_t sb = smem_u32(dsm);

    int b = blockIdx.z, h = blockIdx.y, q0 = blockIdx.x * 128;
    int tid = threadIdx.x, wid = tid >> 5, lid = tid & 31;
    int wr = wid * 16;

    // Q prologue (hi+lo)
#pragma unroll
    for (int grp = 0; grp < 2; grp++) {
        const fp16* base = grp ? ql : qh;
        uint32_t ab = grp ? (uint32_t)AQL : (uint32_t)AQH;
#pragma unroll
        for (int j = 0; j < 8; j++) {
            int rem = tid + j * 256;
            int r = rem >> 4, cch = rem & 15;
            CP16(sb + (ab + (uint32_t)(r * 136 + cch * 8)) * 2,
                 base + (size_t)(b * SQL + q0 + r) * DIM + h * HD + cch * 8);
        }
    }

    auto load_stage = [&](int kt, int st) {
#pragma unroll
        for (int grp = 0; grp < 2; grp++) {
            const fp16* base = grp ? vv : kk;
            uint32_t ab = grp ? (uint32_t)AV(st) : (uint32_t)AK(st);
#pragma unroll
            for (int j = 0; j < 4; j++) {
                int rem = tid + j * 256;
                int r = rem >> 4, cch = rem & 15;
                CP16(sb + (ab + (uint32_t)(r * 136 + cch * 8)) * 2,
                     base + (size_t)(b * SKV + kt + r) * DIM + h * HD + cch * 8);
            }
        }
        if (tid < 64) {
            int kidx = kt + tid;
            const float* srcm;
            if (kidx < SP)           srcm = pmask + b * SP + kidx;
            else if (kidx < SP + SS) srcm = smask + b * SS + (kidx - SP);
            else                     srcm = mmask + b * SMm + (kidx - SP - SS);
            CP4(sb + AMSK_BYTES + st * 256 + tid * 4, srcm);
        }
    };

    float qm2[2];
    qm2[0] = qmask[b * SQL + q0 + wr + (lid >> 2)];
    qm2[1] = qmask[b * SQL + q0 + wr + (lid >> 2) + 8];

    float m2[2] = { -1e30f, -1e30f }, l2[2] = { 0.f, 0.f };
    float o[16][4];
#pragma unroll
    for (int ni = 0; ni < 16; ni++)
#pragma unroll
        for (int r = 0; r < 4; r++) o[ni][r] = 0.f;

    load_stage(0, 0);
    CP_COMMIT();

    for (int t = 0; t < NKT; t++) {
        int st = t & 1;
        CP_WAIT(0);
        __syncthreads();
        if (t + 1 < NKT) { load_stage((t + 1) * 64, st ^ 1); CP_COMMIT(); }

        // ---- S = Qh*K + Ql*K ----
        float cs[8][4];
#pragma unroll
        for (int ni = 0; ni < 8; ni++)
#pragma unroll
            for (int r = 0; r < 4; r++) cs[ni][r] = 0.f;

        uint32_t akb = sb + (uint32_t)AK(st) * 2;
#pragma unroll
        for (int ko = 0; ko < 8; ko++) {
            uint32_t aoff = (uint32_t)((wr + (lid & 15)) * 136 + ko * 16 + ((lid >> 4) << 3)) * 2;
            uint32_t aqh[4], aql[4];
            ldmx4(aqh, sb + AQH * 2 + aoff);
            ldmx4(aql, sb + (uint32_t)AQL * 2 + aoff);
#pragma unroll
            for (int p = 0; p < 4; p++) {
                uint32_t brow = (uint32_t)(p * 16 + (lid & 7) + ((lid >> 4) << 3));
                uint32_t boff = (brow * 136 + ko * 16 + (((lid >> 3) & 1) << 3)) * 2;
                uint32_t b4[4];
                ldmx4(b4, akb + boff);
#pragma unroll
                for (int half = 0; half < 2; half++) {
                    float* cc = cs[p * 2 + half];
                    mma_f16(cc, aqh, &b4[half * 2]);
                    mma_f16(cc, aql, &b4[half * 2]);
                }
            }
        }

        // ---- mask + online softmax ----
        const float* kmf = (const float*)(dsm + AMSK_BYTES + st * 256);
#pragma unroll
        for (int ni = 0; ni < 8; ni++) {
            int c0 = ni * 8 + (lid & 3) * 2;
            float km0 = kmf[c0], km1 = kmf[c0 + 1];
            if (qm2[0] == 0.f || km0 == 0.f) cs[ni][0] = -1e30f;
            if (qm2[0] == 0.f || km1 == 0.f) cs[ni][1] = -1e30f;
            if (qm2[1] == 0.f || km0 == 0.f) cs[ni][2] = -1e30f;
            if (qm2[1] == 0.f || km1 == 0.f) cs[ni][3] = -1e30f;
        }
#pragma unroll
        for (int rh = 0; rh < 2; rh++) {
            float mt = -1e30f;
#pragma unroll
            for (int ni = 0; ni < 8; ni++)
                mt = fmaxf(mt, fmaxf(cs[ni][rh * 2], cs[ni][rh * 2 + 1]));
            mt = fmaxf(mt, __shfl_xor_sync(0xffffffffu, mt, 1));
            mt = fmaxf(mt, __shfl_xor_sync(0xffffffffu, mt, 2));
            float nm = fmaxf(m2[rh], mt);
            float al = __expf(m2[rh] - nm);
            float ps = 0.f;
#pragma unroll
            for (int ni = 0; ni < 8; ni++) {
                float p0 = __expf(cs[ni][rh * 2] - nm);
                float p1 = __expf(cs[ni][rh * 2 + 1] - nm);
                cs[ni][rh * 2] = p0; cs[ni][rh * 2 + 1] = p1;
                ps += p0 + p1;
            }
            ps += __shfl_xor_sync(0xffffffffu, ps, 1);
            ps += __shfl_xor_sync(0xffffffffu, ps, 2);
            l2[rh] = l2[rh] * al + ps;
            m2[rh] = nm;
#pragma unroll
            for (int ni = 0; ni < 16; ni++) {
                o[ni][rh * 2] *= al; o[ni][rh * 2 + 1] *= al;
            }
        }

        // ---- PV: O += Ph*V + Pl*V (V row-major, trans ldmatrix) ----
        uint32_t avb = sb + (uint32_t)AV(st) * 2;
#pragma unroll
        for (int kchunk = 0; kchunk < 4; kchunk++) {
            int t0 = 2 * kchunk, t1 = 2 * kchunk + 1;
            uint32_t pah[4], pal[4];
            {
                fp16 h00, l00, h01, l01, h10, l10, h11, l11;
                split2(cs[t0][0], h00, l00); split2(cs[t0][1], h01, l01);
                split2(cs[t0][2], h10, l10); split2(cs[t0][3], h11, l11);
                pah[0] = pack2(h00, h01); pal[0] = pack2(l00, l01);
                pah[1] = pack2(h10, h11); pal[1] = pack2(l10, l11);
                split2(cs[t1][0], h00, l00); split2(cs[t1][1], h01, l01);
                split2(cs[t1][2], h10, l10); split2(cs[t1][3], h11, l11);
                pah[2] = pack2(h00, h01); pal[2] = pack2(l00, l01);
                pah[3] = pack2(h10, h11); pal[3] = pack2(l10, l11);
            }
#pragma unroll
            for (int p = 0; p < 8; p++) {
                uint32_t kv = (uint32_t)(kchunk * 16 + ((lid >> 3) & 1) * 8 + (lid & 7));
                uint32_t d  = (uint32_t)(p * 16 + (((lid >> 4) & 1) << 3));
                uint32_t off = (kv * 136 + d) * 2;
                uint32_t bv4[4];
                ldmx4t(bv4, avb + off);
#pragma unroll
                for (int half = 0; half < 2; half++) {
                    float* oo = o[p * 2 + half];
                    mma_f16(oo, pah, &bv4[half * 2]);
                    mma_f16(oo, pal, &bv4[half * 2]);
                }
            }
        }
    }

    // ---- epilogue: o/l -> split fp16 ----
#pragma unroll
    for (int rh = 0; rh < 2; rh++) {
        float inv = 1.f / l2[rh];
        int row = q0 + wr + (lid >> 2) + rh * 8;
#pragma unroll
        for (int ni = 0; ni < 16; ni++) {
            int col = h * HD + ni * 8 + (lid & 3) * 2;
            size_t off = (size_t)(b * SQL + row) * DIM + col;
            fp16 h0, l0, h1, l1;
            split2(o[ni][rh * 2] * inv, h0, l0);
            split2(o[ni][rh * 2 + 1] * inv, h1, l1);
            *(uint32_t*)&ch[off] = pack2(h0, h1);
            *(uint32_t*)&cl[off] = pack2(l0, l1);
        }
    }
}

// ---------------- launch ----------------
extern "C" void kernel_launch(void* const* d_in, const int* in_sizes, int n_in,
                              void* d_out, int out_size)
{
    const float* x   = (const float*)d_in[0];
    const float* pkv = (const float*)d_in[1];
    const float* skv = (const float*)d_in[2];
    const float* mkv = (const float*)d_in[3];
    const float* qm  = (const float*)d_in[4];
    const float* pm  = (const float*)d_in[5];
    const float* smk = (const float*)d_in[6];
    const float* mmk = (const float*)d_in[7];
    const float* rw  = (const float*)d_in[8];
    const float* Wq  = (const float*)d_in[9];
    const float* bq  = (const float*)d_in[10];
    const float* Wkp = (const float*)d_in[11];
    const float* bkp = (const float*)d_in[12];
    const float* Wvp = (const float*)d_in[13];
    const float* bvp = (const float*)d_in[14];
    const float* Wks = (const float*)d_in[15];
    const float* bks = (const float*)d_in[16];
    const float* Wvs = (const float*)d_in[17];
    const float* bvs = (const float*)d_in[18];
    const float* Wkm = (const float*)d_in[19];
    const float* bkm = (const float*)d_in[20];
    const float* Wvm = (const float*)d_in[21];
    const float* bvm = (const float*)d_in[22];
    const float* Wo  = (const float*)d_in[23];
    const float* bo  = (const float*)d_in[24];
    const float* lg  = (const float*)d_in[25];
    const float* lb  = (const float*)d_in[26];
    const float* W1  = (const float*)d_in[27];
    const float* W2  = (const float*)d_in[28];
    const float* ga  = (const float*)d_in[29];
    const float* gf  = (const float*)d_in[30];
    float* out = (float*)d_out;

    float* hb;
    cudaGetSymbolAddress((void**)&hb, g_h);

    fp16 *xnh, *xnl, *pkh, *pkl, *skh, *skl, *mkh, *mkl, *cth, *ctl, *lnh, *lnl, *mdh, *mdl;
    cudaGetSymbolAddress((void**)&xnh, g_xnh); cudaGetSymbolAddress((void**)&xnl, g_xnl);
    cudaGetSymbolAddress((void**)&pkh, g_pkh); cudaGetSymbolAddress((void**)&pkl, g_pkl);
    cudaGetSymbolAddress((void**)&skh, g_skh); cudaGetSymbolAddress((void**)&skl, g_skl);
    cudaGetSymbolAddress((void**)&mkh, g_mkh); cudaGetSymbolAddress((void**)&mkl, g_mkl);
    cudaGetSymbolAddress((void**)&cth, g_cth); cudaGetSymbolAddress((void**)&ctl, g_ctl);
    cudaGetSymbolAddress((void**)&lnh, g_lnh); cudaGetSymbolAddress((void**)&lnl, g_lnl);
    cudaGetSymbolAddress((void**)&mdh, g_mdh); cudaGetSymbolAddress((void**)&mdl, g_mdl);

    fp16 *qh, *ql, *k1, *v1;
    cudaGetSymbolAddress((void**)&qh, g_qh); cudaGetSymbolAddress((void**)&ql, g_ql);
    cudaGetSymbolAddress((void**)&k1, g_k1); cudaGetSymbolAddress((void**)&v1, g_v1);

    fp16 *wq, *kp, *vp, *ks, *vs, *km, *vm, *wo, *w1, *w2;
    cudaGetSymbolAddress((void**)&wq, g_wq);
    cudaGetSymbolAddress((void**)&kp, g_kp); cudaGetSymbolAddress((void**)&vp, g_vp);
    cudaGetSymbolAddress((void**)&ks, g_ks); cudaGetSymbolAddress((void**)&vs, g_vs);
    cudaGetSymbolAddress((void**)&km, g_km); cudaGetSymbolAddress((void**)&vm, g_vm);
    cudaGetSymbolAddress((void**)&wo, g_wo);
    cudaGetSymbolAddress((void**)&w1, g_w1); cudaGetSymbolAddress((void**)&w2, g_w2);

    size_t gemm_sh = 2 * STGB;   // 60 KB
    cudaFuncSetAttribute(gemm_mma, cudaFuncAttributeMaxDynamicSharedMemorySize, (int)gemm_sh);
    cudaFuncSetAttribute(attn_tc, cudaFuncAttributeMaxDynamicSharedMemorySize, ATT_SMEM);

    const int NS = 1 << 30;

    // Launches 1-5: prep needed for Q gemm (so launch #6 = gemm_mma for ncu -s 5 -c 1)
    rms_split_kernel<<<BN * SQL, 256>>>(x, rw, xnh, xnl);
    split_kernel<<<(BN * SP * DP) / 256,   256>>>(pkv, pkh, pkl, BN * SP * DP);
    split_kernel<<<(BN * SS * DS) / 256,   256>>>(skv, skh, skl, BN * SS * DS);
    split_kernel<<<(BN * SMm * DMm) / 256, 256>>>(mkv, mkh, mkl, BN * SMm * DMm);
    tsplit_kernel<<<dim3(DIM / 32, DIM / 32),  256>>>(Wq, wq, DIM, DIM);

    // #6: Q projection (scaled 0.25 -> split)
    gemm_mma<<<dim3(DIM / 128, 16, 1), 256, gemm_sh>>>(
        xnh, xnl, 0, wq, wq, bq, bq, nullptr, nullptr,
        nullptr, qh, ql, qh, ql, 0, BN * SQL, DIM, DIM, 0.25f, 4, NS);

    // remaining weight transposes
    tsplit_kernel<<<dim3(DIM / 32, DP / 32),   256>>>(Wkp, kp, DP,    DIM);
    tsplit_kernel<<<dim3(DIM / 32, DP / 32),   256>>>(Wvp, vp, DP,    DIM);
    tsplit_kernel<<<dim3(DIM / 32, DS / 32),   256>>>(Wks, ks, DS,    DIM);
    tsplit_kernel<<<dim3(DIM / 32, DS / 32),   256>>>(Wvs, vs, DS,    DIM);
    tsplit_kernel<<<dim3(DIM / 32, DMm / 32),  256>>>(Wkm, km, DMm,   DIM);
    tsplit_kernel<<<dim3(DIM / 32, DMm / 32),  256>>>(Wvm, vm, DMm,   DIM);
    tsplit_kernel<<<dim3(DIM / 32, DIM / 32),  256>>>(Wo,  wo, DIM,   DIM);
    tsplit_kernel<<<dim3(INNER / 32, DIM / 32), 256>>>(W1, w1, DIM,   INNER);
    tsplit_kernel<<<dim3(DIM / 32, INNER / 32), 256>>>(W2, w2, INNER, DIM);

    // merged K|V projections per segment (N-split at DIM), single-fp16 outputs
    gemm_mma<<<dim3(2 * DIM / 128, SP / 128, BN), 256, gemm_sh>>>(
        pkh, pkl, (long)SP * DP, kp, vp, bkp, bvp, nullptr, nullptr,
        nullptr, k1, nullptr, v1, nullptr, (long)SKV * DIM, SP, DIM, DP, 1.f, 6, DIM);
    gemm_mma<<<dim3(2 * DIM / 128, SS / 128, BN), 256, gemm_sh>>>(
        skh, skl, (long)SS * DS, ks, vs, bks, bvs, nullptr, nullptr,
        nullptr, k1 + (size_t)SP * DIM, nullptr, v1 + (size_t)SP * DIM, nullptr,
        (long)SKV * DIM, SS, DIM, DS, 1.f, 6, DIM);
    gemm_mma<<<dim3(2 * DIM / 128, SMm / 128, BN), 256, gemm_sh>>>(
        mkh, mkl, (long)SMm * DMm, km, vm, bkm, bvm, nullptr, nullptr,
        nullptr, k1 + (size_t)(SP + SS) * DIM, nullptr, v1 + (size_t)(SP + SS) * DIM, nullptr,
        (long)SKV * DIM, SMm, DIM, DMm, 1.f, 6, DIM);

    // flash attention -> ctx split
    attn_tc<<<dim3(SQL / 128, NH, BN), 256, ATT_SMEM>>>(qh, ql, k1, v1,
                                                        qm, pm, smk, mmk, cth, ctl);

    // Wo projection + gated residual
    gemm_mma<<<dim3(DIM / 128, 16, 1), 256, gemm_sh>>>(
        cth, ctl, 0, wo, wo, bo, bo, x, ga,
        hb, nullptr, nullptr, nullptr, nullptr, 0, BN * SQL, DIM, DIM, 1.f, 1, NS);

    // LayerNorm -> split
    ln_split_kernel<<<BN * SQL, 256>>>(hb, lg, lb, lnh, lnl);

    // FFW up + GELU -> split
    gemm_mma<<<dim3(INNER / 128, 16, 1), 256, gemm_sh>>>(
        lnh, lnl, 0, w1, w1, nullptr, nullptr, nullptr, nullptr,
        nullptr, mdh, mdl, mdh, mdl, 0, BN * SQL, INNER, DIM, 1.f, 2, NS);

    // FFW down + gated residual -> out
    gemm_mma<<<dim3(DIM / 128, 16, 1), 256, gemm_sh>>>(
        mdh, mdl, 0, w2, w2, nullptr, nullptr, hb, gf,
        out, nullptr, nullptr, nullptr, nullptr, 0, BN * SQL, DIM, INNER, 1.f, 3, NS);
}

// round 8
// speedup vs baseline: 2.3082x; 1.6694x over previous
#include <cuda_runtime.h>
#include <cuda_fp16.h>
#include <math.h>
#include <stdint.h>

// ---------------- problem constants ----------------
#define BN    2
#define SQL   1024
#define DIM   2048
#define NH    16
#define HD    128
#define SP    1024
#define SS    1024
#define SMm   512
#define SKV   2560
#define DP    1280
#define DS    1024
#define DMm   768
#define INNER 8192

typedef __half fp16;

// ---------------- scratch ----------------
__device__ __align__(256) float g_h  [BN*SQL*DIM];

// fp16 activations
__device__ __align__(256) fp16 g_xn [BN*SQL*DIM];
__device__ __align__(256) fp16 g_pk [BN*SP*DP];
__device__ __align__(256) fp16 g_sk [BN*SS*DS];
__device__ __align__(256) fp16 g_mk [BN*SMm*DMm];
__device__ __align__(256) fp16 g_ct [BN*SQL*DIM];
__device__ __align__(256) fp16 g_ln [BN*SQL*DIM];
__device__ __align__(256) fp16 g_md [BN*SQL*INNER];

// q (pre-scaled 0.25), k, v fp16, row-major [S][DIM]
__device__ __align__(256) fp16 g_q  [BN*SQL*DIM];
__device__ __align__(256) fp16 g_k1 [BN*SKV*DIM];
__device__ __align__(256) fp16 g_v1 [BN*SKV*DIM];

// transposed fp16 weights ([N][K] K-major)
__device__ __align__(256) fp16 g_wq [DIM*DIM];
__device__ __align__(256) fp16 g_kp [DIM*DP];
__device__ __align__(256) fp16 g_vp [DIM*DP];
__device__ __align__(256) fp16 g_ks [DIM*DS];
__device__ __align__(256) fp16 g_vs [DIM*DS];
__device__ __align__(256) fp16 g_km [DIM*DMm];
__device__ __align__(256) fp16 g_vm [DIM*DMm];
__device__ __align__(256) fp16 g_wo [DIM*DIM];
__device__ __align__(256) fp16 g_w1 [INNER*DIM];
__device__ __align__(256) fp16 g_w2 [DIM*INNER];

// ---------------- helpers ----------------
#define CP16(dst, src) asm volatile("cp.async.cg.shared.global [%0], [%1], 16;" :: "r"(dst), "l"(src))
#define CP4(dst, src)  asm volatile("cp.async.ca.shared.global [%0], [%1], 4;"  :: "r"(dst), "l"(src))
#define CP_COMMIT()  asm volatile("cp.async.commit_group;" ::: "memory")
#define CP_WAIT(n)   asm volatile("cp.async.wait_group %0;" :: "n"(n) : "memory")

__device__ __forceinline__ uint32_t smem_u32(const void* p) {
    uint32_t a;
    asm("{ .reg .u64 t; cvta.to.shared.u64 t, %1; cvt.u32.u64 %0, t; }" : "=r"(a) : "l"(p));
    return a;
}
__device__ __forceinline__ void mma_f16(float* c, const uint32_t* a, const uint32_t* b) {
    asm volatile("mma.sync.aligned.m16n8k16.row.col.f32.f16.f16.f32 "
        "{%0,%1,%2,%3}, {%4,%5,%6,%7}, {%8,%9}, {%0,%1,%2,%3};"
        : "+f"(c[0]), "+f"(c[1]), "+f"(c[2]), "+f"(c[3])
        : "r"(a[0]), "r"(a[1]), "r"(a[2]), "r"(a[3]), "r"(b[0]), "r"(b[1]));
}
__device__ __forceinline__ void ldmx4(uint32_t* r, uint32_t addr) {
    asm volatile("ldmatrix.sync.aligned.m8n8.x4.shared.b16 {%0,%1,%2,%3}, [%4];"
        : "=r"(r[0]), "=r"(r[1]), "=r"(r[2]), "=r"(r[3]) : "r"(addr));
}
__device__ __forceinline__ void ldmx4t(uint32_t* r, uint32_t addr) {
    asm volatile("ldmatrix.sync.aligned.m8n8.x4.trans.shared.b16 {%0,%1,%2,%3}, [%4];"
        : "=r"(r[0]), "=r"(r[1]), "=r"(r[2]), "=r"(r[3]) : "r"(addr));
}
__device__ __forceinline__ uint32_t pack2(fp16 a, fp16 b) {
    __half2 t(a, b);
    return *(uint32_t*)&t;
}

// ---------------- prep kernels ----------------
__global__ __launch_bounds__(256) void cvt_kernel(const float* __restrict__ x,
                                                  fp16* __restrict__ y, int n) {
    int i = blockIdx.x * 256 + threadIdx.x;
    if (i < n) y[i] = __float2half_rn(x[i]);
}

// transpose to fp16: W[K][N] -> [N][K]
__global__ __launch_bounds__(256) void tcvt_kernel(const float* __restrict__ W,
                                                   fp16* __restrict__ outw, int K, int N) {
    __shared__ float t[32][33];
    int n0 = blockIdx.x * 32, k0 = blockIdx.y * 32;
    int tx = threadIdx.x & 31, ty = threadIdx.x >> 5;
#pragma unroll
    for (int r = 0; r < 32; r += 8)
        t[ty + r][tx] = W[(size_t)(k0 + ty + r) * N + n0 + tx];
    __syncthreads();
#pragma unroll
    for (int r = 0; r < 32; r += 8)
        outw[(size_t)(n0 + ty + r) * K + k0 + tx] = __float2half_rn(t[tx][ty + r]);
}

__global__ __launch_bounds__(256) void rms_cvt_kernel(
    const float* __restrict__ x, const float* __restrict__ w, fp16* __restrict__ y) {
    __shared__ float red[256];
    int row = blockIdx.x;
    const float* xr = x + (size_t)row * DIM;
    float ss = 0.f;
    for (int c = threadIdx.x; c < DIM; c += 256) { float v = xr[c]; ss += v * v; }
    red[threadIdx.x] = ss; __syncthreads();
    for (int s = 128; s > 0; s >>= 1) {
        if (threadIdx.x < s) red[threadIdx.x] += red[threadIdx.x + s];
        __syncthreads();
    }
    float inv = rsqrtf(red[0] / (float)DIM + 1e-6f);
    for (int c = threadIdx.x; c < DIM; c += 256)
        y[(size_t)row * DIM + c] = __float2half_rn(xr[c] * inv * w[c]);
}

__global__ __launch_bounds__(256) void ln_cvt_kernel(
    const float* __restrict__ x, const float* __restrict__ g, const float* __restrict__ b,
    fp16* __restrict__ y) {
    __shared__ float r1[256], r2[256];
    int row = blockIdx.x;
    const float* xr = x + (size_t)row * DIM;
    float s1 = 0.f, s2 = 0.f;
    for (int c = threadIdx.x; c < DIM; c += 256) { float v = xr[c]; s1 += v; s2 += v * v; }
    r1[threadIdx.x] = s1; r2[threadIdx.x] = s2; __syncthreads();
    for (int s = 128; s > 0; s >>= 1) {
        if (threadIdx.x < s) { r1[threadIdx.x] += r1[threadIdx.x + s]; r2[threadIdx.x] += r2[threadIdx.x + s]; }
        __syncthreads();
    }
    float mu = r1[0] / (float)DIM;
    float rstd = rsqrtf(r2[0] / (float)DIM - mu * mu + 1e-5f);
    for (int c = threadIdx.x; c < DIM; c += 256)
        y[(size_t)row * DIM + c] = __float2half_rn((xr[c] - mu) * rstd * g[c] + b[c]);
}

// ---------------- mma.sync fp16 GEMM ----------------
// C[M,N] = A[M,K] @ B^T ; A,B fp16, fp32 accumulate.
// epi: 0: C=acc+bias (f32) | 1: C=res+tanh(g)*(acc+bias) | 2: gelu->fp16 | 3: C=res+tanh(g)*acc
//      4: (acc+bias)*scale -> fp16
// Dual-output: when n0 >= nsplit, use B2/bias2/O2 with n0 -= nsplit.
#define RS    40
#define ARRB  10240
#define STGB  20480

__global__ __launch_bounds__(256) void gemm_mma(
    const fp16* __restrict__ A, long aStride,
    const fp16* __restrict__ B, const fp16* __restrict__ B2,
    const float* __restrict__ bias, const float* __restrict__ bias2,
    const float* __restrict__ res, const float* __restrict__ gate,
    float* __restrict__ C, fp16* __restrict__ O, fp16* __restrict__ O2,
    long cStride, int M, int N, int K, float scale, int epi, int nsplit)
{
    extern __shared__ __align__(128) char dsm[];

    int tid = threadIdx.x, wid = tid >> 5, lid = tid & 31;
    int wm = wid & 3, wn = wid >> 2;
    int m0 = blockIdx.y << 7, n0 = blockIdx.x << 7;

    if (n0 >= nsplit) {
        B = B2; bias = bias2; O = O2;
        n0 -= nsplit;
    }

    A += (size_t)blockIdx.z * aStride;
    if (C) C += (size_t)blockIdx.z * cStride;
    if (O) O += (size_t)blockIdx.z * cStride;

    uint32_t sbase = smem_u32(dsm);
    const fp16* aptr[2] = { A + (size_t)m0 * K, B + (size_t)n0 * K };

    auto load_stage = [&](int k0, int st) {
        uint32_t base = sbase + (uint32_t)st * STGB;
#pragma unroll
        for (int arr = 0; arr < 2; arr++) {
            const fp16* p = aptr[arr];
            uint32_t ab = base + (uint32_t)arr * ARRB;
#pragma unroll
            for (int j = 0; j < 2; j++) {
                int rem = tid + j * 256;
                int row = rem >> 2, ch = rem & 3;
                CP16(ab + (uint32_t)(row * RS * 2 + ch * 16), p + (size_t)row * K + k0 + ch * 8);
            }
        }
    };

    float c[2][8][4];
#pragma unroll
    for (int mi = 0; mi < 2; mi++)
#pragma unroll
        for (int ni = 0; ni < 8; ni++)
#pragma unroll
            for (int r = 0; r < 4; r++) c[mi][ni][r] = 0.f;

    const int nt = K >> 5;
    load_stage(0, 0);
    CP_COMMIT();

    for (int t = 0; t < nt; t++) {
        int st = t & 1;
        if (t + 1 < nt) {
            load_stage((t + 1) << 5, st ^ 1);
            CP_COMMIT();
            CP_WAIT(1);
        } else {
            CP_WAIT(0);
        }
        __syncthreads();

        uint32_t A_b = sbase + (uint32_t)st * STGB;
        uint32_t B_b = A_b + ARRB;

#pragma unroll
        for (int ks = 0; ks < 2; ks++) {
            int ko = ks * 16;
            uint32_t ah[2][4];
#pragma unroll
            for (int mi = 0; mi < 2; mi++) {
                uint32_t aoff = (uint32_t)((wm * 32 + mi * 16 + (lid & 15)) * RS + ko + ((lid >> 4) << 3)) * 2;
                ldmx4(ah[mi], A_b + aoff);
            }
#pragma unroll
            for (int nh2 = 0; nh2 < 2; nh2++) {
                uint32_t b4[2][4];
#pragma unroll
                for (int p = 0; p < 2; p++) {
                    uint32_t brow = (uint32_t)(wn * 64 + nh2 * 32 + p * 16 + (lid & 7) + ((lid >> 4) << 3));
                    uint32_t boff = (brow * RS + ko + (((lid >> 3) & 1) << 3)) * 2;
                    ldmx4(b4[p], B_b + boff);
                }
#pragma unroll
                for (int mi = 0; mi < 2; mi++)
#pragma unroll
                    for (int nj = 0; nj < 4; nj++)
                        mma_f16(c[mi][nh2 * 4 + nj], ah[mi], &b4[nj >> 1][(nj & 1) * 2]);
            }
        }
        __syncthreads();
    }

    float gv = (epi == 1 || epi == 3) ? tanhf(*gate) : 0.f;
#pragma unroll
    for (int mi = 0; mi < 2; mi++) {
#pragma unroll
        for (int ni = 0; ni < 8; ni++) {
            int col = n0 + wn * 64 + ni * 8 + (lid & 3) * 2;
            float bcol0 = 0.f, bcol1 = 0.f;
            if (epi != 2 && epi != 3) { bcol0 = bias[col]; bcol1 = bias[col + 1]; }
#pragma unroll
            for (int rh = 0; rh < 2; rh++) {
                int m = m0 + wm * 32 + mi * 16 + (lid >> 2) + rh * 8;
                float v0 = c[mi][ni][rh * 2 + 0];
                float v1 = c[mi][ni][rh * 2 + 1];
                size_t o = (size_t)m * N + col;
                if (epi == 0) {
                    C[o] = v0 + bcol0; C[o + 1] = v1 + bcol1;
                } else if (epi == 1) {
                    C[o]     = res[o]     + gv * (v0 + bcol0);
                    C[o + 1] = res[o + 1] + gv * (v1 + bcol1);
                } else if (epi == 2) {
                    float g0 = 0.5f * v0 * (1.f + erff(v0 * 0.70710678118654752f));
                    float g1 = 0.5f * v1 * (1.f + erff(v1 * 0.70710678118654752f));
                    *(uint32_t*)&O[o] = pack2(__float2half_rn(g0), __float2half_rn(g1));
                } else if (epi == 3) {
                    C[o]     = res[o]     + gv * v0;
                    C[o + 1] = res[o + 1] + gv * v1;
                } else { // epi == 4
                    *(uint32_t*)&O[o] = pack2(__float2half_rn((v0 + bcol0) * scale),
                                              __float2half_rn((v1 + bcol1) * scale));
                }
            }
        }
    }
}

// ---------------- tensor-core flash attention (plain fp16) ----------------
// Br=128 (8 warps x 16 rows), Bc=64, HD=128.
#define AQ 0
#define AK(st) (17408 + (st) * 8704)
#define AV(st) (34816 + (st) * 8704)
#define AMSK_BYTES 104448
#define ATT_SMEM (AMSK_BYTES + 512)
#define NKT (SKV / 64)

__global__ __launch_bounds__(256) void attn_tc(
    const fp16* __restrict__ qv, const fp16* __restrict__ kk, const fp16* __restrict__ vv,
    const float* __restrict__ qmask, const float* __restrict__ pmask,
    const float* __restrict__ smask, const float* __restrict__ mmask,
    fp16* __restrict__ co)
{
    extern __shared__ __align__(128) char dsm[];
    uint32_t sb = smem_u32(dsm);

    int b = blockIdx.z, h = blockIdx.y, q0 = blockIdx.x * 128;
    int tid = threadIdx.x, wid = tid >> 5, lid = tid & 31;
    int wr = wid * 16;

    // Q prologue
#pragma unroll
    for (int j = 0; j < 8; j++) {
        int rem = tid + j * 256;
        int r = rem >> 4, cch = rem & 15;
        CP16(sb + (uint32_t)(AQ + r * 136 + cch * 8) * 2,
             qv + (size_t)(b * SQL + q0 + r) * DIM + h * HD + cch * 8);
    }

    auto load_stage = [&](int kt, int st) {
#pragma unroll
        for (int grp = 0; grp < 2; grp++) {
            const fp16* base = grp ? vv : kk;
            uint32_t ab = grp ? (uint32_t)AV(st) : (uint32_t)AK(st);
#pragma unroll
            for (int j = 0; j < 4; j++) {
                int rem = tid + j * 256;
                int r = rem >> 4, cch = rem & 15;
                CP16(sb + (ab + (uint32_t)(r * 136 + cch * 8)) * 2,
                     base + (size_t)(b * SKV + kt + r) * DIM + h * HD + cch * 8);
            }
        }
        if (tid < 64) {
            int kidx = kt + tid;
            const float* srcm;
            if (kidx < SP)           srcm = pmask + b * SP + kidx;
            else if (kidx < SP + SS) srcm = smask + b * SS + (kidx - SP);
            else                     srcm = mmask + b * SMm + (kidx - SP - SS);
            CP4(sb + AMSK_BYTES + st * 256 + tid * 4, srcm);
        }
    };

    float qm2[2];
    qm2[0] = qmask[b * SQL + q0 + wr + (lid >> 2)];
    qm2[1] = qmask[b * SQL + q0 + wr + (lid >> 2) + 8];

    float m2[2] = { -1e30f, -1e30f }, l2[2] = { 0.f, 0.f };
    float o[16][4];
#pragma unroll
    for (int ni = 0; ni < 16; ni++)
#pragma unroll
        for (int r = 0; r < 4; r++) o[ni][r] = 0.f;

    load_stage(0, 0);
    CP_COMMIT();

    for (int t = 0; t < NKT; t++) {
        int st = t & 1;
        CP_WAIT(0);
        __syncthreads();
        if (t + 1 < NKT) { load_stage((t + 1) * 64, st ^ 1); CP_COMMIT(); }

        // ---- S = Q*K ----
        float cs[8][4];
#pragma unroll
        for (int ni = 0; ni < 8; ni++)
#pragma unroll
            for (int r = 0; r < 4; r++) cs[ni][r] = 0.f;

        uint32_t akb = sb + (uint32_t)AK(st) * 2;
#pragma unroll
        for (int ko = 0; ko < 8; ko++) {
            uint32_t aoff = (uint32_t)((wr + (lid & 15)) * 136 + ko * 16 + ((lid >> 4) << 3)) * 2;
            uint32_t aq[4];
            ldmx4(aq, sb + AQ * 2 + aoff);
#pragma unroll
            for (int p = 0; p < 4; p++) {
                uint32_t brow = (uint32_t)(p * 16 + (lid & 7) + ((lid >> 4) << 3));
                uint32_t boff = (brow * 136 + ko * 16 + (((lid >> 3) & 1) << 3)) * 2;
                uint32_t b4[4];
                ldmx4(b4, akb + boff);
#pragma unroll
                for (int half = 0; half < 2; half++)
                    mma_f16(cs[p * 2 + half], aq, &b4[half * 2]);
            }
        }

        // ---- mask + online softmax ----
        const float* kmf = (const float*)(dsm + AMSK_BYTES + st * 256);
#pragma unroll
        for (int ni = 0; ni < 8; ni++) {
            int c0 = ni * 8 + (lid & 3) * 2;
            float km0 = kmf[c0], km1 = kmf[c0 + 1];
            if (qm2[0] == 0.f || km0 == 0.f) cs[ni][0] = -1e30f;
            if (qm2[0] == 0.f || km1 == 0.f) cs[ni][1] = -1e30f;
            if (qm2[1] == 0.f || km0 == 0.f) cs[ni][2] = -1e30f;
            if (qm2[1] == 0.f || km1 == 0.f) cs[ni][3] = -1e30f;
        }
#pragma unroll
        for (int rh = 0; rh < 2; rh++) {
            float mt = -1e30f;
#pragma unroll
            for (int ni = 0; ni < 8; ni++)
                mt = fmaxf(mt, fmaxf(cs[ni][rh * 2], cs[ni][rh * 2 + 1]));
            mt = fmaxf(mt, __shfl_xor_sync(0xffffffffu, mt, 1));
            mt = fmaxf(mt, __shfl_xor_sync(0xffffffffu, mt, 2));
            float nm = fmaxf(m2[rh], mt);
            float al = __expf(m2[rh] - nm);
            float ps = 0.f;
#pragma unroll
            for (int ni = 0; ni < 8; ni++) {
                float p0 = __expf(cs[ni][rh * 2] - nm);
                float p1 = __expf(cs[ni][rh * 2 + 1] - nm);
                cs[ni][rh * 2] = p0; cs[ni][rh * 2 + 1] = p1;
                ps += p0 + p1;
            }
            ps += __shfl_xor_sync(0xffffffffu, ps, 1);
            ps += __shfl_xor_sync(0xffffffffu, ps, 2);
            l2[rh] = l2[rh] * al + ps;
            m2[rh] = nm;
#pragma unroll
            for (int ni = 0; ni < 16; ni++) {
                o[ni][rh * 2] *= al; o[ni][rh * 2 + 1] *= al;
            }
        }

        // ---- PV: O += P*V (V row-major, trans ldmatrix) ----
        uint32_t avb = sb + (uint32_t)AV(st) * 2;
#pragma unroll
        for (int kchunk = 0; kchunk < 4; kchunk++) {
            int t0 = 2 * kchunk, t1 = 2 * kchunk + 1;
            uint32_t pa[4];
            pa[0] = pack2(__float2half_rn(cs[t0][0]), __float2half_rn(cs[t0][1]));
            pa[1] = pack2(__float2half_rn(cs[t0][2]), __float2half_rn(cs[t0][3]));
            pa[2] = pack2(__float2half_rn(cs[t1][0]), __float2half_rn(cs[t1][1]));
            pa[3] = pack2(__float2half_rn(cs[t1][2]), __float2half_rn(cs[t1][3]));
#pragma unroll
            for (int p = 0; p < 8; p++) {
                uint32_t kv = (uint32_t)(kchunk * 16 + ((lid >> 3) & 1) * 8 + (lid & 7));
                uint32_t d  = (uint32_t)(p * 16 + (((lid >> 4) & 1) << 3));
                uint32_t off = (kv * 136 + d) * 2;
                uint32_t bv4[4];
                ldmx4t(bv4, avb + off);
#pragma unroll
                for (int half = 0; half < 2; half++)
                    mma_f16(o[p * 2 + half], pa, &bv4[half * 2]);
            }
        }
    }

    // ---- epilogue -> fp16 ctx ----
#pragma unroll
    for (int rh = 0; rh < 2; rh++) {
        float inv = 1.f / l2[rh];
        int row = q0 + wr + (lid >> 2) + rh * 8;
#pragma unroll
        for (int ni = 0; ni < 16; ni++) {
            int col = h * HD + ni * 8 + (lid & 3) * 2;
            size_t off = (size_t)(b * SQL + row) * DIM + col;
            *(uint32_t*)&co[off] = pack2(__float2half_rn(o[ni][rh * 2] * inv),
                                         __float2half_rn(o[ni][rh * 2 + 1] * inv));
        }
    }
}

// ---------------- launch ----------------
extern "C" void kernel_launch(void* const* d_in, const int* in_sizes, int n_in,
                              void* d_out, int out_size)
{
    const float* x   = (const float*)d_in[0];
    const float* pkv = (const float*)d_in[1];
    const float* skv = (const float*)d_in[2];
    const float* mkv = (const float*)d_in[3];
    const float* qm  = (const float*)d_in[4];
    const float* pm  = (const float*)d_in[5];
    const float* smk = (const float*)d_in[6];
    const float* mmk = (const float*)d_in[7];
    const float* rw  = (const float*)d_in[8];
    const float* Wq  = (const float*)d_in[9];
    const float* bq  = (const float*)d_in[10];
    const float* Wkp = (const float*)d_in[11];
    const float* bkp = (const float*)d_in[12];
    const float* Wvp = (const float*)d_in[13];
    const float* bvp = (const float*)d_in[14];
    const float* Wks = (const float*)d_in[15];
    const float* bks = (const float*)d_in[16];
    const float* Wvs = (const float*)d_in[17];
    const float* bvs = (const float*)d_in[18];
    const float* Wkm = (const float*)d_in[19];
    const float* bkm = (const float*)d_in[20];
    const float* Wvm = (const float*)d_in[21];
    const float* bvm = (const float*)d_in[22];
    const float* Wo  = (const float*)d_in[23];
    const float* bo  = (const float*)d_in[24];
    const float* lg  = (const float*)d_in[25];
    const float* lb  = (const float*)d_in[26];
    const float* W1  = (const float*)d_in[27];
    const float* W2  = (const float*)d_in[28];
    const float* ga  = (const float*)d_in[29];
    const float* gf  = (const float*)d_in[30];
    float* out = (float*)d_out;

    float* hb;
    cudaGetSymbolAddress((void**)&hb, g_h);

    fp16 *xn, *pk, *sk, *mk, *ct, *ln, *md, *qv, *k1, *v1;
    cudaGetSymbolAddress((void**)&xn, g_xn);
    cudaGetSymbolAddress((void**)&pk, g_pk);
    cudaGetSymbolAddress((void**)&sk, g_sk);
    cudaGetSymbolAddress((void**)&mk, g_mk);
    cudaGetSymbolAddress((void**)&ct, g_ct);
    cudaGetSymbolAddress((void**)&ln, g_ln);
    cudaGetSymbolAddress((void**)&md, g_md);
    cudaGetSymbolAddress((void**)&qv, g_q);
    cudaGetSymbolAddress((void**)&k1, g_k1);
    cudaGetSymbolAddress((void**)&v1, g_v1);

    fp16 *wq, *kp, *vp, *ks, *vs, *km, *vm, *wo, *w1, *w2;
    cudaGetSymbolAddress((void**)&wq, g_wq);
    cudaGetSymbolAddress((void**)&kp, g_kp); cudaGetSymbolAddress((void**)&vp, g_vp);
    cudaGetSymbolAddress((void**)&ks, g_ks); cudaGetSymbolAddress((void**)&vs, g_vs);
    cudaGetSymbolAddress((void**)&km, g_km); cudaGetSymbolAddress((void**)&vm, g_vm);
    cudaGetSymbolAddress((void**)&wo, g_wo);
    cudaGetSymbolAddress((void**)&w1, g_w1); cudaGetSymbolAddress((void**)&w2, g_w2);

    size_t gemm_sh = 2 * STGB;   // 40 KB
    cudaFuncSetAttribute(gemm_mma, cudaFuncAttributeMaxDynamicSharedMemorySize, (int)gemm_sh);
    cudaFuncSetAttribute(attn_tc, cudaFuncAttributeMaxDynamicSharedMemorySize, ATT_SMEM);

    const int NS = 1 << 30;

    // launches 1-5 (prep for Q gemm; #6 = gemm_mma for ncu -s 5 -c 1)
    rms_cvt_kernel<<<BN * SQL, 256>>>(x, rw, xn);
    cvt_kernel<<<(BN * SP * DP) / 256,   256>>>(pkv, pk, BN * SP * DP);
    cvt_kernel<<<(BN * SS * DS) / 256,   256>>>(skv, sk, BN * SS * DS);
    cvt_kernel<<<(BN * SMm * DMm) / 256, 256>>>(mkv, mk, BN * SMm * DMm);
    tcvt_kernel<<<dim3(DIM / 32, DIM / 32), 256>>>(Wq, wq, DIM, DIM);

    // #6: Q projection (scaled 0.25 -> fp16)
    gemm_mma<<<dim3(DIM / 128, 16, 1), 256, gemm_sh>>>(
        xn, 0, wq, wq, bq, bq, nullptr, nullptr,
        nullptr, qv, qv, 0, BN * SQL, DIM, DIM, 0.25f, 4, NS);

    // remaining weight transposes
    tcvt_kernel<<<dim3(DIM / 32, DP / 32),   256>>>(Wkp, kp, DP,    DIM);
    tcvt_kernel<<<dim3(DIM / 32, DP / 32),   256>>>(Wvp, vp, DP,    DIM);
    tcvt_kernel<<<dim3(DIM / 32, DS / 32),   256>>>(Wks, ks, DS,    DIM);
    tcvt_kernel<<<dim3(DIM / 32, DS / 32),   256>>>(Wvs, vs, DS,    DIM);
    tcvt_kernel<<<dim3(DIM / 32, DMm / 32),  256>>>(Wkm, km, DMm,   DIM);
    tcvt_kernel<<<dim3(DIM / 32, DMm / 32),  256>>>(Wvm, vm, DMm,   DIM);
    tcvt_kernel<<<dim3(DIM / 32, DIM / 32),  256>>>(Wo,  wo, DIM,   DIM);
    tcvt_kernel<<<dim3(INNER / 32, DIM / 32), 256>>>(W1, w1, DIM,   INNER);
    tcvt_kernel<<<dim3(DIM / 32, INNER / 32), 256>>>(W2, w2, INNER, DIM);

    // merged K|V projections per segment (N-split at DIM)
    gemm_mma<<<dim3(2 * DIM / 128, SP / 128, BN), 256, gemm_sh>>>(
        pk, (long)SP * DP, kp, vp, bkp, bvp, nullptr, nullptr,
        nullptr, k1, v1, (long)SKV * DIM, SP, DIM, DP, 1.f, 4, DIM);
    gemm_mma<<<dim3(2 * DIM / 128, SS / 128, BN), 256, gemm_sh>>>(
        sk, (long)SS * DS, ks, vs, bks, bvs, nullptr, nullptr,
        nullptr, k1 + (size_t)SP * DIM, v1 + (size_t)SP * DIM,
        (long)SKV * DIM, SS, DIM, DS, 1.f, 4, DIM);
    gemm_mma<<<dim3(2 * DIM / 128, SMm / 128, BN), 256, gemm_sh>>>(
        mk, (long)SMm * DMm, km, vm, bkm, bvm, nullptr, nullptr,
        nullptr, k1 + (size_t)(SP + SS) * DIM, v1 + (size_t)(SP + SS) * DIM,
        (long)SKV * DIM, SMm, DIM, DMm, 1.f, 4, DIM);

    // flash attention -> fp16 ctx
    attn_tc<<<dim3(SQL / 128, NH, BN), 256, ATT_SMEM>>>(qv, k1, v1,
                                                        qm, pm, smk, mmk, ct);

    // Wo projection + gated residual
    gemm_mma<<<dim3(DIM / 128, 16, 1), 256, gemm_sh>>>(
        ct, 0, wo, wo, bo, bo, x, ga,
        hb, nullptr, nullptr, 0, BN * SQL, DIM, DIM, 1.f, 1, NS);

    // LayerNorm -> fp16
    ln_cvt_kernel<<<BN * SQL, 256>>>(hb, lg, lb, ln);

    // FFW up + GELU -> fp16
    gemm_mma<<<dim3(INNER / 128, 16, 1), 256, gemm_sh>>>(
        ln, 0, w1, w1, nullptr, nullptr, nullptr, nullptr,
        nullptr, md, md, 0, BN * SQL, INNER, DIM, 1.f, 2, NS);

    // FFW down + gated residual -> out
    gemm_mma<<<dim3(DIM / 128, 16, 1), 256, gemm_sh>>>(
        md, 0, w2, w2, nullptr, nullptr, hb, gf,
        out, nullptr, nullptr, 0, BN * SQL, DIM, INNER, 1.f, 3, NS);
}

// round 9
// speedup vs baseline: 2.3959x; 1.0380x over previous
#include <cuda_runtime.h>
#include <cuda_fp16.h>
#include <math.h>
#include <stdint.h>

// ---------------- problem constants ----------------
#define BN    2
#define SQL   1024
#define DIM   2048
#define NH    16
#define HD    128
#define SP    1024
#define SS    1024
#define SMm   512
#define SKV   2560
#define DP    1280
#define DS    1024
#define DMm   768
#define INNER 8192

typedef __half fp16;

// ---------------- scratch ----------------
__device__ __align__(256) float g_h  [BN*SQL*DIM];

__device__ __align__(256) fp16 g_xn [BN*SQL*DIM];
__device__ __align__(256) fp16 g_pk [BN*SP*DP];
__device__ __align__(256) fp16 g_sk [BN*SS*DS];
__device__ __align__(256) fp16 g_mk [BN*SMm*DMm];
__device__ __align__(256) fp16 g_ct [BN*SQL*DIM];
__device__ __align__(256) fp16 g_ln [BN*SQL*DIM];
__device__ __align__(256) fp16 g_md [BN*SQL*INNER];

__device__ __align__(256) fp16 g_q  [BN*SQL*DIM];
__device__ __align__(256) fp16 g_k1 [BN*SKV*DIM];
__device__ __align__(256) fp16 g_v1 [BN*SKV*DIM];

__device__ __align__(256) fp16 g_wq [DIM*DIM];
__device__ __align__(256) fp16 g_kp [DIM*DP];
__device__ __align__(256) fp16 g_vp [DIM*DP];
__device__ __align__(256) fp16 g_ks [DIM*DS];
__device__ __align__(256) fp16 g_vs [DIM*DS];
__device__ __align__(256) fp16 g_km [DIM*DMm];
__device__ __align__(256) fp16 g_vm [DIM*DMm];
__device__ __align__(256) fp16 g_wo [DIM*DIM];
__device__ __align__(256) fp16 g_w1 [INNER*DIM];
__device__ __align__(256) fp16 g_w2 [DIM*INNER];

// ---------------- helpers ----------------
#define CP16(dst, src) asm volatile("cp.async.cg.shared.global [%0], [%1], 16;" :: "r"(dst), "l"(src))
#define CP4(dst, src)  asm volatile("cp.async.ca.shared.global [%0], [%1], 4;"  :: "r"(dst), "l"(src))
#define CP_COMMIT()  asm volatile("cp.async.commit_group;" ::: "memory")
#define CP_WAIT(n)   asm volatile("cp.async.wait_group %0;" :: "n"(n) : "memory")

__device__ __forceinline__ uint32_t smem_u32(const void* p) {
    uint32_t a;
    asm("{ .reg .u64 t; cvta.to.shared.u64 t, %1; cvt.u32.u64 %0, t; }" : "=r"(a) : "l"(p));
    return a;
}
__device__ __forceinline__ void mma_f16(float* c, const uint32_t* a, const uint32_t* b) {
    asm volatile("mma.sync.aligned.m16n8k16.row.col.f32.f16.f16.f32 "
        "{%0,%1,%2,%3}, {%4,%5,%6,%7}, {%8,%9}, {%0,%1,%2,%3};"
        : "+f"(c[0]), "+f"(c[1]), "+f"(c[2]), "+f"(c[3])
        : "r"(a[0]), "r"(a[1]), "r"(a[2]), "r"(a[3]), "r"(b[0]), "r"(b[1]));
}
__device__ __forceinline__ void ldmx4(uint32_t* r, uint32_t addr) {
    asm volatile("ldmatrix.sync.aligned.m8n8.x4.shared.b16 {%0,%1,%2,%3}, [%4];"
        : "=r"(r[0]), "=r"(r[1]), "=r"(r[2]), "=r"(r[3]) : "r"(addr));
}
__device__ __forceinline__ void ldmx4t(uint32_t* r, uint32_t addr) {
    asm volatile("ldmatrix.sync.aligned.m8n8.x4.trans.shared.b16 {%0,%1,%2,%3}, [%4];"
        : "=r"(r[0]), "=r"(r[1]), "=r"(r[2]), "=r"(r[3]) : "r"(addr));
}
__device__ __forceinline__ uint32_t pack2(fp16 a, fp16 b) {
    __half2 t(a, b);
    return *(uint32_t*)&t;
}

// ---------------- prep kernels ----------------
// merged vectorized fp32->fp16 convert: 3 segments, 1024 elems/block
__global__ __launch_bounds__(256) void cvt_all(
    const float* __restrict__ x0, fp16* __restrict__ y0, int c0,
    const float* __restrict__ x1, fp16* __restrict__ y1, int c1,
    const float* __restrict__ x2, fp16* __restrict__ y2, int c2)
{
    int b = blockIdx.x;
    const float* x; fp16* y; int base;
    if (b < c0)      { x = x0; y = y0; base = b; }
    else if (b < c1) { x = x1; y = y1; base = b - c0; }
    else             { x = x2; y = y2; base = b - c1; }
    size_t i = ((size_t)base * 256 + threadIdx.x) * 4;
    float4 v = *(const float4*)(x + i);
    uint2 o;
    o.x = pack2(__float2half_rn(v.x), __float2half_rn(v.y));
    o.y = pack2(__float2half_rn(v.z), __float2half_rn(v.w));
    *(uint2*)(y + i) = o;
}

// merged weight transpose+convert: W[K][N] fp32 -> out[N][K] fp16, 10 segments
struct WEnt { const float* W; fp16* O; int K; int N; int cum; };
struct WTab { WEnt e[10]; };

__global__ __launch_bounds__(256) void tcvt_all(WTab tab) {
    __shared__ float t[32][33];
    int lin = blockIdx.x;
    int s = 0;
#pragma unroll
    for (int i = 1; i < 10; i++) if (lin >= tab.e[i].cum) s = i;
    const float* W = tab.e[s].W;
    fp16* O = tab.e[s].O;
    int K = tab.e[s].K, N = tab.e[s].N;
    int local = lin - tab.e[s].cum;
    int nx = N >> 5;
    int n0 = (local % nx) * 32, k0 = (local / nx) * 32;
    int tx = threadIdx.x & 31, ty = threadIdx.x >> 5;
#pragma unroll
    for (int r = 0; r < 32; r += 8)
        t[ty + r][tx] = W[(size_t)(k0 + ty + r) * N + n0 + tx];
    __syncthreads();
#pragma unroll
    for (int r = 0; r < 32; r += 8)
        O[(size_t)(n0 + ty + r) * K + k0 + tx] = __float2half_rn(t[tx][ty + r]);
}

__global__ __launch_bounds__(256) void rms_cvt_kernel(
    const float* __restrict__ x, const float* __restrict__ w, fp16* __restrict__ y) {
    __shared__ float red[256];
    int row = blockIdx.x;
    const float* xr = x + (size_t)row * DIM;
    float ss = 0.f;
    for (int c = threadIdx.x; c < DIM; c += 256) { float v = xr[c]; ss += v * v; }
    red[threadIdx.x] = ss; __syncthreads();
    for (int s = 128; s > 0; s >>= 1) {
        if (threadIdx.x < s) red[threadIdx.x] += red[threadIdx.x + s];
        __syncthreads();
    }
    float inv = rsqrtf(red[0] / (float)DIM + 1e-6f);
    for (int c = threadIdx.x; c < DIM; c += 256)
        y[(size_t)row * DIM + c] = __float2half_rn(xr[c] * inv * w[c]);
}

__global__ __launch_bounds__(256) void ln_cvt_kernel(
    const float* __restrict__ x, const float* __restrict__ g, const float* __restrict__ b,
    fp16* __restrict__ y) {
    __shared__ float r1[256], r2[256];
    int row = blockIdx.x;
    const float* xr = x + (size_t)row * DIM;
    float s1 = 0.f, s2 = 0.f;
    for (int c = threadIdx.x; c < DIM; c += 256) { float v = xr[c]; s1 += v; s2 += v * v; }
    r1[threadIdx.x] = s1; r2[threadIdx.x] = s2; __syncthreads();
    for (int s = 128; s > 0; s >>= 1) {
        if (threadIdx.x < s) { r1[threadIdx.x] += r1[threadIdx.x + s]; r2[threadIdx.x] += r2[threadIdx.x + s]; }
        __syncthreads();
    }
    float mu = r1[0] / (float)DIM;
    float rstd = rsqrtf(r2[0] / (float)DIM - mu * mu + 1e-5f);
    for (int c = threadIdx.x; c < DIM; c += 256)
        y[(size_t)row * DIM + c] = __float2half_rn((xr[c] - mu) * rstd * g[c] + b[c]);
}

// ---------------- mma.sync fp16 GEMM (3-stage, 1 barrier/iter) ----------------
// epi: 0: C=acc+bias | 1: C=res+tanh(g)*(acc+bias) | 2: gelu->fp16 | 3: C=res+tanh(g)*acc
//      4: (acc+bias)*scale -> fp16
#define RS    40
#define ARRB  10240
#define STGB  20480
#define NSTG  3

__global__ __launch_bounds__(256) void gemm_mma(
    const fp16* __restrict__ A, long aStride,
    const fp16* __restrict__ B, const fp16* __restrict__ B2,
    const float* __restrict__ bias, const float* __restrict__ bias2,
    const float* __restrict__ res, const float* __restrict__ gate,
    float* __restrict__ C, fp16* __restrict__ O, fp16* __restrict__ O2,
    long cStride, int M, int N, int K, float scale, int epi, int nsplit)
{
    extern __shared__ __align__(128) char dsm[];

    int tid = threadIdx.x, wid = tid >> 5, lid = tid & 31;
    int wm = wid & 3, wn = wid >> 2;
    int m0 = blockIdx.y << 7, n0 = blockIdx.x << 7;

    if (n0 >= nsplit) {
        B = B2; bias = bias2; O = O2;
        n0 -= nsplit;
    }

    A += (size_t)blockIdx.z * aStride;
    if (C) C += (size_t)blockIdx.z * cStride;
    if (O) O += (size_t)blockIdx.z * cStride;

    uint32_t sbase = smem_u32(dsm);
    const fp16* aptr[2] = { A + (size_t)m0 * K, B + (size_t)n0 * K };

    auto load_stage = [&](int k0, int st) {
        uint32_t base = sbase + (uint32_t)st * STGB;
#pragma unroll
        for (int arr = 0; arr < 2; arr++) {
            const fp16* p = aptr[arr];
            uint32_t ab = base + (uint32_t)arr * ARRB;
#pragma unroll
            for (int j = 0; j < 2; j++) {
                int rem = tid + j * 256;
                int row = rem >> 2, ch = rem & 3;
                CP16(ab + (uint32_t)(row * RS * 2 + ch * 16), p + (size_t)row * K + k0 + ch * 8);
            }
        }
    };

    float c[2][8][4];
#pragma unroll
    for (int mi = 0; mi < 2; mi++)
#pragma unroll
        for (int ni = 0; ni < 8; ni++)
#pragma unroll
            for (int r = 0; r < 4; r++) c[mi][ni][r] = 0.f;

    const int nt = K >> 5;
    load_stage(0, 0);
    CP_COMMIT();
    load_stage(32, 1);
    CP_COMMIT();

    int st = 0;
    for (int t = 0; t < nt; t++) {
        if (t + 1 < nt) { CP_WAIT(1); } else { CP_WAIT(0); }
        __syncthreads();
        if (t + 2 < nt) {
            int st2 = st + 2; if (st2 >= NSTG) st2 -= NSTG;
            load_stage((t + 2) << 5, st2);
            CP_COMMIT();
        }

        uint32_t A_b = sbase + (uint32_t)st * STGB;
        uint32_t B_b = A_b + ARRB;

#pragma unroll
        for (int ks = 0; ks < 2; ks++) {
            int ko = ks * 16;
            uint32_t ah[2][4];
#pragma unroll
            for (int mi = 0; mi < 2; mi++) {
                uint32_t aoff = (uint32_t)((wm * 32 + mi * 16 + (lid & 15)) * RS + ko + ((lid >> 4) << 3)) * 2;
                ldmx4(ah[mi], A_b + aoff);
            }
#pragma unroll
            for (int nh2 = 0; nh2 < 2; nh2++) {
                uint32_t b4[2][4];
#pragma unroll
                for (int p = 0; p < 2; p++) {
                    uint32_t brow = (uint32_t)(wn * 64 + nh2 * 32 + p * 16 + (lid & 7) + ((lid >> 4) << 3));
                    uint32_t boff = (brow * RS + ko + (((lid >> 3) & 1) << 3)) * 2;
                    ldmx4(b4[p], B_b + boff);
                }
#pragma unroll
                for (int mi = 0; mi < 2; mi++)
#pragma unroll
                    for (int nj = 0; nj < 4; nj++)
                        mma_f16(c[mi][nh2 * 4 + nj], ah[mi], &b4[nj >> 1][(nj & 1) * 2]);
            }
        }
        if (++st >= NSTG) st = 0;
    }

    float gv = (epi == 1 || epi == 3) ? tanhf(*gate) : 0.f;
#pragma unroll
    for (int mi = 0; mi < 2; mi++) {
#pragma unroll
        for (int ni = 0; ni < 8; ni++) {
            int col = n0 + wn * 64 + ni * 8 + (lid & 3) * 2;
            float bcol0 = 0.f, bcol1 = 0.f;
            if (epi != 2 && epi != 3) { bcol0 = bias[col]; bcol1 = bias[col + 1]; }
#pragma unroll
            for (int rh = 0; rh < 2; rh++) {
                int m = m0 + wm * 32 + mi * 16 + (lid >> 2) + rh * 8;
                float v0 = c[mi][ni][rh * 2 + 0];
                float v1 = c[mi][ni][rh * 2 + 1];
                size_t o = (size_t)m * N + col;
                if (epi == 0) {
                    C[o] = v0 + bcol0; C[o + 1] = v1 + bcol1;
                } else if (epi == 1) {
                    C[o]     = res[o]     + gv * (v0 + bcol0);
                    C[o + 1] = res[o + 1] + gv * (v1 + bcol1);
                } else if (epi == 2) {
                    float g0 = 0.5f * v0 * (1.f + erff(v0 * 0.70710678118654752f));
                    float g1 = 0.5f * v1 * (1.f + erff(v1 * 0.70710678118654752f));
                    *(uint32_t*)&O[o] = pack2(__float2half_rn(g0), __float2half_rn(g1));
                } else if (epi == 3) {
                    C[o]     = res[o]     + gv * v0;
                    C[o + 1] = res[o + 1] + gv * v1;
                } else { // epi == 4
                    *(uint32_t*)&O[o] = pack2(__float2half_rn((v0 + bcol0) * scale),
                                              __float2half_rn((v1 + bcol1) * scale));
                }
            }
        }
    }
}

// ---------------- tensor-core flash attention (fp16) ----------------
#define AQ 0
#define AK(st) (17408 + (st) * 8704)
#define AV(st) (34816 + (st) * 8704)
#define AMSK_BYTES 104448
#define ATT_SMEM (AMSK_BYTES + 512)
#define NKT (SKV / 64)

__global__ __launch_bounds__(256) void attn_tc(
    const fp16* __restrict__ qv, const fp16* __restrict__ kk, const fp16* __restrict__ vv,
    const float* __restrict__ qmask, const float* __restrict__ pmask,
    const float* __restrict__ smask, const float* __restrict__ mmask,
    fp16* __restrict__ co)
{
    extern __shared__ __align__(128) char dsm[];
    uint32_t sb = smem_u32(dsm);

    int b = blockIdx.z, h = blockIdx.y, q0 = blockIdx.x * 128;
    int tid = threadIdx.x, wid = tid >> 5, lid = tid & 31;
    int wr = wid * 16;

#pragma unroll
    for (int j = 0; j < 8; j++) {
        int rem = tid + j * 256;
        int r = rem >> 4, cch = rem & 15;
        CP16(sb + (uint32_t)(AQ + r * 136 + cch * 8) * 2,
             qv + (size_t)(b * SQL + q0 + r) * DIM + h * HD + cch * 8);
    }

    auto load_stage = [&](int kt, int st) {
#pragma unroll
        for (int grp = 0; grp < 2; grp++) {
            const fp16* base = grp ? vv : kk;
            uint32_t ab = grp ? (uint32_t)AV(st) : (uint32_t)AK(st);
#pragma unroll
            for (int j = 0; j < 4; j++) {
                int rem = tid + j * 256;
                int r = rem >> 4, cch = rem & 15;
                CP16(sb + (ab + (uint32_t)(r * 136 + cch * 8)) * 2,
                     base + (size_t)(b * SKV + kt + r) * DIM + h * HD + cch * 8);
            }
        }
        if (tid < 64) {
            int kidx = kt + tid;
            const float* srcm;
            if (kidx < SP)           srcm = pmask + b * SP + kidx;
            else if (kidx < SP + SS) srcm = smask + b * SS + (kidx - SP);
            else                     srcm = mmask + b * SMm + (kidx - SP - SS);
            CP4(sb + AMSK_BYTES + st * 256 + tid * 4, srcm);
        }
    };

    float qm2[2];
    qm2[0] = qmask[b * SQL + q0 + wr + (lid >> 2)];
    qm2[1] = qmask[b * SQL + q0 + wr + (lid >> 2) + 8];

    float m2[2] = { -1e30f, -1e30f }, l2[2] = { 0.f, 0.f };
    float o[16][4];
#pragma unroll
    for (int ni = 0; ni < 16; ni++)
#pragma unroll
        for (int r = 0; r < 4; r++) o[ni][r] = 0.f;

    load_stage(0, 0);
    CP_COMMIT();

    for (int t = 0; t < NKT; t++) {
        int st = t & 1;
        CP_WAIT(0);
        __syncthreads();
        if (t + 1 < NKT) { load_stage((t + 1) * 64, st ^ 1); CP_COMMIT(); }

        float cs[8][4];
#pragma unroll
        for (int ni = 0; ni < 8; ni++)
#pragma unroll
            for (int r = 0; r < 4; r++) cs[ni][r] = 0.f;

        uint32_t akb = sb + (uint32_t)AK(st) * 2;
#pragma unroll
        for (int ko = 0; ko < 8; ko++) {
            uint32_t aoff = (uint32_t)((wr + (lid & 15)) * 136 + ko * 16 + ((lid >> 4) << 3)) * 2;
            uint32_t aq[4];
            ldmx4(aq, sb + AQ * 2 + aoff);
#pragma unroll
            for (int p = 0; p < 4; p++) {
                uint32_t brow = (uint32_t)(p * 16 + (lid & 7) + ((lid >> 4) << 3));
                uint32_t boff = (brow * 136 + ko * 16 + (((lid >> 3) & 1) << 3)) * 2;
                uint32_t b4[4];
                ldmx4(b4, akb + boff);
#pragma unroll
                for (int half = 0; half < 2; half++)
                    mma_f16(cs[p * 2 + half], aq, &b4[half * 2]);
            }
        }

        const float* kmf = (const float*)(dsm + AMSK_BYTES + st * 256);
#pragma unroll
        for (int ni = 0; ni < 8; ni++) {
            int c0 = ni * 8 + (lid & 3) * 2;
            float km0 = kmf[c0], km1 = kmf[c0 + 1];
            if (qm2[0] == 0.f || km0 == 0.f) cs[ni][0] = -1e30f;
            if (qm2[0] == 0.f || km1 == 0.f) cs[ni][1] = -1e30f;
            if (qm2[1] == 0.f || km0 == 0.f) cs[ni][2] = -1e30f;
            if (qm2[1] == 0.f || km1 == 0.f) cs[ni][3] = -1e30f;
        }
#pragma unroll
        for (int rh = 0; rh < 2; rh++) {
            float mt = -1e30f;
#pragma unroll
            for (int ni = 0; ni < 8; ni++)
                mt = fmaxf(mt, fmaxf(cs[ni][rh * 2], cs[ni][rh * 2 + 1]));
            mt = fmaxf(mt, __shfl_xor_sync(0xffffffffu, mt, 1));
            mt = fmaxf(mt, __shfl_xor_sync(0xffffffffu, mt, 2));
            float nm = fmaxf(m2[rh], mt);
            float al = __expf(m2[rh] - nm);
            float ps = 0.f;
#pragma unroll
            for (int ni = 0; ni < 8; ni++) {
                float p0 = __expf(cs[ni][rh * 2] - nm);
                float p1 = __expf(cs[ni][rh * 2 + 1] - nm);
                cs[ni][rh * 2] = p0; cs[ni][rh * 2 + 1] = p1;
                ps += p0 + p1;
            }
            ps += __shfl_xor_sync(0xffffffffu, ps, 1);
            ps += __shfl_xor_sync(0xffffffffu, ps, 2);
            l2[rh] = l2[rh] * al + ps;
            m2[rh] = nm;
#pragma unroll
            for (int ni = 0; ni < 16; ni++) {
                o[ni][rh * 2] *= al; o[ni][rh * 2 + 1] *= al;
            }
        }

        uint32_t avb = sb + (uint32_t)AV(st) * 2;
#pragma unroll
        for (int kchunk = 0; kchunk < 4; kchunk++) {
            int t0 = 2 * kchunk, t1 = 2 * kchunk + 1;
            uint32_t pa[4];
            pa[0] = pack2(__float2half_rn(cs[t0][0]), __float2half_rn(cs[t0][1]));
            pa[1] = pack2(__float2half_rn(cs[t0][2]), __float2half_rn(cs[t0][3]));
            pa[2] = pack2(__float2half_rn(cs[t1][0]), __float2half_rn(cs[t1][1]));
            pa[3] = pack2(__float2half_rn(cs[t1][2]), __float2half_rn(cs[t1][3]));
#pragma unroll
            for (int p = 0; p < 8; p++) {
                uint32_t kv = (uint32_t)(kchunk * 16 + ((lid >> 3) & 1) * 8 + (lid & 7));
                uint32_t d  = (uint32_t)(p * 16 + (((lid >> 4) & 1) << 3));
                uint32_t off = (kv * 136 + d) * 2;
                uint32_t bv4[4];
                ldmx4t(bv4, avb + off);
#pragma unroll
                for (int half = 0; half < 2; half++)
                    mma_f16(o[p * 2 + half], pa, &bv4[half * 2]);
            }
        }
    }

#pragma unroll
    for (int rh = 0; rh < 2; rh++) {
        float inv = 1.f / l2[rh];
        int row = q0 + wr + (lid >> 2) + rh * 8;
#pragma unroll
        for (int ni = 0; ni < 16; ni++) {
            int col = h * HD + ni * 8 + (lid & 3) * 2;
            size_t off = (size_t)(b * SQL + row) * DIM + col;
            *(uint32_t*)&co[off] = pack2(__float2half_rn(o[ni][rh * 2] * inv),
                                         __float2half_rn(o[ni][rh * 2 + 1] * inv));
        }
    }
}

// ---------------- launch ----------------
extern "C" void kernel_launch(void* const* d_in, const int* in_sizes, int n_in,
                              void* d_out, int out_size)
{
    const float* x   = (const float*)d_in[0];
    const float* pkv = (const float*)d_in[1];
    const float* skv = (const float*)d_in[2];
    const float* mkv = (const float*)d_in[3];
    const float* qm  = (const float*)d_in[4];
    const float* pm  = (const float*)d_in[5];
    const float* smk = (const float*)d_in[6];
    const float* mmk = (const float*)d_in[7];
    const float* rw  = (const float*)d_in[8];
    const float* Wq  = (const float*)d_in[9];
    const float* bq  = (const float*)d_in[10];
    const float* Wkp = (const float*)d_in[11];
    const float* bkp = (const float*)d_in[12];
    const float* Wvp = (const float*)d_in[13];
    const float* bvp = (const float*)d_in[14];
    const float* Wks = (const float*)d_in[15];
    const float* bks = (const float*)d_in[16];
    const float* Wvs = (const float*)d_in[17];
    const float* bvs = (const float*)d_in[18];
    const float* Wkm = (const float*)d_in[19];
    const float* bkm = (const float*)d_in[20];
    const float* Wvm = (const float*)d_in[21];
    const float* bvm = (const float*)d_in[22];
    const float* Wo  = (const float*)d_in[23];
    const float* bo  = (const float*)d_in[24];
    const float* lg  = (const float*)d_in[25];
    const float* lb  = (const float*)d_in[26];
    const float* W1  = (const float*)d_in[27];
    const float* W2  = (const float*)d_in[28];
    const float* ga  = (const float*)d_in[29];
    const float* gf  = (const float*)d_in[30];
    float* out = (float*)d_out;

    float* hb;
    cudaGetSymbolAddress((void**)&hb, g_h);

    fp16 *xn, *pk, *sk, *mk, *ct, *ln, *md, *qv, *k1, *v1;
    cudaGetSymbolAddress((void**)&xn, g_xn);
    cudaGetSymbolAddress((void**)&pk, g_pk);
    cudaGetSymbolAddress((void**)&sk, g_sk);
    cudaGetSymbolAddress((void**)&mk, g_mk);
    cudaGetSymbolAddress((void**)&ct, g_ct);
    cudaGetSymbolAddress((void**)&ln, g_ln);
    cudaGetSymbolAddress((void**)&md, g_md);
    cudaGetSymbolAddress((void**)&qv, g_q);
    cudaGetSymbolAddress((void**)&k1, g_k1);
    cudaGetSymbolAddress((void**)&v1, g_v1);

    fp16 *wq, *kp, *vp, *ks, *vs, *km, *vm, *wo, *w1, *w2;
    cudaGetSymbolAddress((void**)&wq, g_wq);
    cudaGetSymbolAddress((void**)&kp, g_kp); cudaGetSymbolAddress((void**)&vp, g_vp);
    cudaGetSymbolAddress((void**)&ks, g_ks); cudaGetSymbolAddress((void**)&vs, g_vs);
    cudaGetSymbolAddress((void**)&km, g_km); cudaGetSymbolAddress((void**)&vm, g_vm);
    cudaGetSymbolAddress((void**)&wo, g_wo);
    cudaGetSymbolAddress((void**)&w1, g_w1); cudaGetSymbolAddress((void**)&w2, g_w2);

    size_t gemm_sh = NSTG * STGB;   // 60 KB
    cudaFuncSetAttribute(gemm_mma, cudaFuncAttributeMaxDynamicSharedMemorySize, (int)gemm_sh);
    cudaFuncSetAttribute(attn_tc, cudaFuncAttributeMaxDynamicSharedMemorySize, ATT_SMEM);

    const int NS = 1 << 30;

    // ---- prep (3 launches) ----
    rms_cvt_kernel<<<BN * SQL, 256>>>(x, rw, xn);

    int c0 = (BN * SP * DP) / 1024;
    int c1 = c0 + (BN * SS * DS) / 1024;
    int c2 = c1 + (BN * SMm * DMm) / 1024;
    cvt_all<<<c2, 256>>>(pkv, pk, c0, skv, sk, c1, mkv, mk, c2);

    WTab tab;
    const float* Ws[10] = { Wq, Wkp, Wvp, Wks, Wvs, Wkm, Wvm, Wo, W1, W2 };
    fp16* Os[10]        = { wq, kp,  vp,  ks,  vs,  km,  vm,  wo, w1, w2 };
    int Kk[10] = { DIM, DP, DP, DS, DS, DMm, DMm, DIM, DIM, INNER };
    int Nn[10] = { DIM, DIM, DIM, DIM, DIM, DIM, DIM, DIM, INNER, DIM };
    int cum = 0;
    for (int i = 0; i < 10; i++) {
        tab.e[i].W = Ws[i]; tab.e[i].O = Os[i];
        tab.e[i].K = Kk[i]; tab.e[i].N = Nn[i];
        tab.e[i].cum = cum;
        cum += (Nn[i] / 32) * (Kk[i] / 32);
    }
    tcvt_all<<<cum, 256>>>(tab);

    // #4: Q projection (scaled 0.25 -> fp16)
    gemm_mma<<<dim3(DIM / 128, 16, 1), 256, gemm_sh>>>(
        xn, 0, wq, wq, bq, bq, nullptr, nullptr,
        nullptr, qv, qv, 0, BN * SQL, DIM, DIM, 0.25f, 4, NS);

    // #5-7: merged K|V projections per segment (N-split at DIM)
    gemm_mma<<<dim3(2 * DIM / 128, SP / 128, BN), 256, gemm_sh>>>(
        pk, (long)SP * DP, kp, vp, bkp, bvp, nullptr, nullptr,
        nullptr, k1, v1, (long)SKV * DIM, SP, DIM, DP, 1.f, 4, DIM);
    gemm_mma<<<dim3(2 * DIM / 128, SS / 128, BN), 256, gemm_sh>>>(
        sk, (long)SS * DS, ks, vs, bks, bvs, nullptr, nullptr,
        nullptr, k1 + (size_t)SP * DIM, v1 + (size_t)SP * DIM,
        (long)SKV * DIM, SS, DIM, DS, 1.f, 4, DIM);
    gemm_mma<<<dim3(2 * DIM / 128, SMm / 128, BN), 256, gemm_sh>>>(
        mk, (long)SMm * DMm, km, vm, bkm, bvm, nullptr, nullptr,
        nullptr, k1 + (size_t)(SP + SS) * DIM, v1 + (size_t)(SP + SS) * DIM,
        (long)SKV * DIM, SMm, DIM, DMm, 1.f, 4, DIM);

    // flash attention -> fp16 ctx
    attn_tc<<<dim3(SQL / 128, NH, BN), 256, ATT_SMEM>>>(qv, k1, v1,
                                                        qm, pm, smk, mmk, ct);

    // Wo projection + gated residual
    gemm_mma<<<dim3(DIM / 128, 16, 1), 256, gemm_sh>>>(
        ct, 0, wo, wo, bo, bo, x, ga,
        hb, nullptr, nullptr, 0, BN * SQL, DIM, DIM, 1.f, 1, NS);

    // LayerNorm -> fp16
    ln_cvt_kernel<<<BN * SQL, 256>>>(hb, lg, lb, ln);

    // FFW up + GELU -> fp16
    gemm_mma<<<dim3(INNER / 128, 16, 1), 256, gemm_sh>>>(
        ln, 0, w1, w1, nullptr, nullptr, nullptr, nullptr,
        nullptr, md, md, 0, BN * SQL, INNER, DIM, 1.f, 2, NS);

    // FFW down + gated residual -> out
    gemm_mma<<<dim3(DIM / 128, 16, 1), 256, gemm_sh>>>(
        md, 0, w2, w2, nullptr, nullptr, hb, gf,
        out, nullptr, nullptr, 0, BN * SQL, DIM, INNER, 1.f, 3, NS);
}

// round 14
// speedup vs baseline: 2.5158x; 1.0500x over previous
#include <cuda_runtime.h>
#include <cuda_fp16.h>
#include <math.h>
#include <stdint.h>

// ---------------- problem constants ----------------
#define BN    2
#define SQL   1024
#define DIM   2048
#define NH    16
#define HD    128
#define SP    1024
#define SS    1024
#define SMm   512
#define SKV   2560
#define DP    1280
#define DS    1024
#define DMm   768
#define INNER 8192

typedef __half fp16;

// ---------------- scratch ----------------
__device__ __align__(256) float g_h  [BN*SQL*DIM];

__device__ __align__(256) fp16 g_xn [BN*SQL*DIM];
__device__ __align__(256) fp16 g_pk [BN*SP*DP];
__device__ __align__(256) fp16 g_sk [BN*SS*DS];
__device__ __align__(256) fp16 g_mk [BN*SMm*DMm];
__device__ __align__(256) fp16 g_ct [BN*SQL*DIM];
__device__ __align__(256) fp16 g_ln [BN*SQL*DIM];
__device__ __align__(256) fp16 g_md [BN*SQL*INNER];

__device__ __align__(256) fp16 g_q  [BN*SQL*DIM];
__device__ __align__(256) fp16 g_k1 [BN*SKV*DIM];
__device__ __align__(256) fp16 g_v1 [BN*SKV*DIM];

__device__ __align__(256) fp16 g_wq [DIM*DIM];
__device__ __align__(256) fp16 g_kp [DIM*DP];
__device__ __align__(256) fp16 g_vp [DIM*DP];
__device__ __align__(256) fp16 g_ks [DIM*DS];
__device__ __align__(256) fp16 g_vs [DIM*DS];
__device__ __align__(256) fp16 g_km [DIM*DMm];
__device__ __align__(256) fp16 g_vm [DIM*DMm];
__device__ __align__(256) fp16 g_wo [DIM*DIM];
__device__ __align__(256) fp16 g_w1 [INNER*DIM];
__device__ __align__(256) fp16 g_w2 [DIM*INNER];

// ---------------- helpers ----------------
#define CP16(dst, src) asm volatile("cp.async.cg.shared.global [%0], [%1], 16;" :: "r"(dst), "l"(src))
#define CP4(dst, src)  asm volatile("cp.async.ca.shared.global [%0], [%1], 4;"  :: "r"(dst), "l"(src))
#define CP_COMMIT()  asm volatile("cp.async.commit_group;" ::: "memory")
#define CP_WAIT(n)   asm volatile("cp.async.wait_group %0;" :: "n"(n) : "memory")

__device__ __forceinline__ uint32_t smem_u32(const void* p) {
    uint32_t a;
    asm("{ .reg .u64 t; cvta.to.shared.u64 t, %1; cvt.u32.u64 %0, t; }" : "=r"(a) : "l"(p));
    return a;
}
__device__ __forceinline__ void mma_f16(float* c, const uint32_t* a, const uint32_t* b) {
    asm volatile("mma.sync.aligned.m16n8k16.row.col.f32.f16.f16.f32 "
        "{%0,%1,%2,%3}, {%4,%5,%6,%7}, {%8,%9}, {%0,%1,%2,%3};"
        : "+f"(c[0]), "+f"(c[1]), "+f"(c[2]), "+f"(c[3])
        : "r"(a[0]), "r"(a[1]), "r"(a[2]), "r"(a[3]), "r"(b[0]), "r"(b[1]));
}
__device__ __forceinline__ void ldmx4(uint32_t* r, uint32_t addr) {
    asm volatile("ldmatrix.sync.aligned.m8n8.x4.shared.b16 {%0,%1,%2,%3}, [%4];"
        : "=r"(r[0]), "=r"(r[1]), "=r"(r[2]), "=r"(r[3]) : "r"(addr));
}
__device__ __forceinline__ void ldmx4t(uint32_t* r, uint32_t addr) {
    asm volatile("ldmatrix.sync.aligned.m8n8.x4.trans.shared.b16 {%0,%1,%2,%3}, [%4];"
        : "=r"(r[0]), "=r"(r[1]), "=r"(r[2]), "=r"(r[3]) : "r"(addr));
}
__device__ __forceinline__ uint32_t pack2(fp16 a, fp16 b) {
    __half2 t(a, b);
    return *(uint32_t*)&t;
}

// ---------------- prep kernels ----------------
__global__ __launch_bounds__(256) void cvt_all(
    const float* __restrict__ x0, fp16* __restrict__ y0, int c0,
    const float* __restrict__ x1, fp16* __restrict__ y1, int c1,
    const float* __restrict__ x2, fp16* __restrict__ y2, int c2)
{
    int b = blockIdx.x;
    const float* x; fp16* y; int base;
    if (b < c0)      { x = x0; y = y0; base = b; }
    else if (b < c1) { x = x1; y = y1; base = b - c0; }
    else             { x = x2; y = y2; base = b - c1; }
    size_t i = ((size_t)base * 256 + threadIdx.x) * 4;
    float4 v = *(const float4*)(x + i);
    uint2 o;
    o.x = pack2(__float2half_rn(v.x), __float2half_rn(v.y));
    o.y = pack2(__float2half_rn(v.z), __float2half_rn(v.w));
    *(uint2*)(y + i) = o;
}

struct WEnt { const float* W; fp16* O; int K; int N; int cum; };
struct WTab { WEnt e[10]; };

__global__ __launch_bounds__(256) void tcvt_all(WTab tab) {
    __shared__ float t[32][33];
    int lin = blockIdx.x;
    int s = 0;
#pragma unroll
    for (int i = 1; i < 10; i++) if (lin >= tab.e[i].cum) s = i;
    const float* W = tab.e[s].W;
    fp16* O = tab.e[s].O;
    int K = tab.e[s].K, N = tab.e[s].N;
    int local = lin - tab.e[s].cum;
    int nx = N >> 5;
    int n0 = (local % nx) * 32, k0 = (local / nx) * 32;
    int tx = threadIdx.x & 31, ty = threadIdx.x >> 5;
#pragma unroll
    for (int r = 0; r < 32; r += 8)
        t[ty + r][tx] = W[(size_t)(k0 + ty + r) * N + n0 + tx];
    __syncthreads();
#pragma unroll
    for (int r = 0; r < 32; r += 8)
        O[(size_t)(n0 + ty + r) * K + k0 + tx] = __float2half_rn(t[tx][ty + r]);
}

__global__ __launch_bounds__(256) void rms_cvt_kernel(
    const float* __restrict__ x, const float* __restrict__ w, fp16* __restrict__ y) {
    __shared__ float red[256];
    int row = blockIdx.x;
    const float* xr = x + (size_t)row * DIM;
    float ss = 0.f;
    for (int c = threadIdx.x; c < DIM; c += 256) { float v = xr[c]; ss += v * v; }
    red[threadIdx.x] = ss; __syncthreads();
    for (int s = 128; s > 0; s >>= 1) {
        if (threadIdx.x < s) red[threadIdx.x] += red[threadIdx.x + s];
        __syncthreads();
    }
    float inv = rsqrtf(red[0] / (float)DIM + 1e-6f);
    for (int c = threadIdx.x; c < DIM; c += 256)
        y[(size_t)row * DIM + c] = __float2half_rn(xr[c] * inv * w[c]);
}

__global__ __launch_bounds__(256) void ln_cvt_kernel(
    const float* __restrict__ x, const float* __restrict__ g, const float* __restrict__ b,
    fp16* __restrict__ y) {
    __shared__ float r1[256], r2[256];
    int row = blockIdx.x;
    const float* xr = x + (size_t)row * DIM;
    float s1 = 0.f, s2 = 0.f;
    for (int c = threadIdx.x; c < DIM; c += 256) { float v = xr[c]; s1 += v; s2 += v * v; }
    r1[threadIdx.x] = s1; r2[threadIdx.x] = s2; __syncthreads();
    for (int s = 128; s > 0; s >>= 1) {
        if (threadIdx.x < s) { r1[threadIdx.x] += r1[threadIdx.x + s]; r2[threadIdx.x] += r2[threadIdx.x + s]; }
        __syncthreads();
    }
    float mu = r1[0] / (float)DIM;
    float rstd = rsqrtf(r2[0] / (float)DIM - mu * mu + 1e-5f);
    for (int c = threadIdx.x; c < DIM; c += 256)
        y[(size_t)row * DIM + c] = __float2half_rn((xr[c] - mu) * rstd * g[c] + b[c]);
}

// ---------------- shared GEMM mainloop (4-stage cp.async pipeline) ----------------
#define RS    40
#define ARRB  10240
#define STGB  20480
#define NSTG  4

__device__ __forceinline__ void gemm_main(
    const fp16* __restrict__ Ab, const fp16* __restrict__ Bb, int K,
    float c[2][8][4], char* dsm, int tid, int wm, int wn, int lid)
{
    uint32_t sbase = smem_u32(dsm);
    const fp16* aptr[2] = { Ab, Bb };

    auto load_stage = [&](int k0, int st) {
        uint32_t base = sbase + (uint32_t)st * STGB;
#pragma unroll
        for (int arr = 0; arr < 2; arr++) {
            const fp16* p = aptr[arr];
            uint32_t ab = base + (uint32_t)arr * ARRB;
#pragma unroll
            for (int j = 0; j < 2; j++) {
                int rem = tid + j * 256;
                int row = rem >> 2, ch = rem & 3;
                CP16(ab + (uint32_t)(row * RS * 2 + ch * 16), p + (size_t)row * K + k0 + ch * 8);
            }
        }
    };

    const int nt = K >> 5;
    load_stage(0, 0);  CP_COMMIT();
    load_stage(32, 1); CP_COMMIT();
    load_stage(64, 2); CP_COMMIT();

    int st = 0;
    for (int t = 0; t < nt; t++) {
        int rem = nt - 1 - t;
        if (rem >= 2)      { CP_WAIT(2); }
        else if (rem == 1) { CP_WAIT(1); }
        else               { CP_WAIT(0); }
        __syncthreads();
        if (t + 3 < nt) {
            load_stage((t + 3) << 5, (st + 3) & 3);
            CP_COMMIT();
        }

        uint32_t A_b = sbase + (uint32_t)st * STGB;
        uint32_t B_b = A_b + ARRB;

#pragma unroll
        for (int ks = 0; ks < 2; ks++) {
            int ko = ks * 16;
            uint32_t ah[2][4];
#pragma unroll
            for (int mi = 0; mi < 2; mi++) {
                uint32_t aoff = (uint32_t)((wm * 32 + mi * 16 + (lid & 15)) * RS + ko + ((lid >> 4) << 3)) * 2;
                ldmx4(ah[mi], A_b + aoff);
            }
#pragma unroll
            for (int nh2 = 0; nh2 < 2; nh2++) {
                uint32_t b4[2][4];
#pragma unroll
                for (int p = 0; p < 2; p++) {
                    uint32_t brow = (uint32_t)(wn * 64 + nh2 * 32 + p * 16 + (lid & 7) + ((lid >> 4) << 3));
                    uint32_t boff = (brow * RS + ko + (((lid >> 3) & 1) << 3)) * 2;
                    ldmx4(b4[p], B_b + boff);
                }
#pragma unroll
                for (int mi = 0; mi < 2; mi++)
#pragma unroll
                    for (int nj = 0; nj < 4; nj++)
                        mma_f16(c[mi][nh2 * 4 + nj], ah[mi], &b4[nj >> 1][(nj & 1) * 2]);
            }
        }
        st = (st + 1) & 3;
    }
}

// ---------------- merged projection GEMM (Q + K|V segments, one launch) ----------------
struct PSeg {
    const fp16* A; const fp16* Bk; const fp16* Bv;
    const float* bk; const float* bv;
    fp16* Ok; fp16* Ov;
    long aStride, cStride;
    int Kdim, nx, nxK, my, cum;
    float scale;
};
struct PTab { PSeg e[4]; };

__global__ __launch_bounds__(256) void gemm_proj(PTab tab) {
    extern __shared__ __align__(128) char dsm[];
    int tid = threadIdx.x, wid = tid >> 5, lid = tid & 31;
    int wm = wid & 3, wn = wid >> 2;

    int bid = blockIdx.x;
    int s = 0;
#pragma unroll
    for (int i = 1; i < 4; i++) if (bid >= tab.e[i].cum) s = i;
    PSeg sg = tab.e[s];
    int local = bid - sg.cum;
    int per = sg.nx * sg.my;
    int z = local / per;
    int rem2 = local - z * per;
    int mb = rem2 / sg.nx;
    int nbk = rem2 - mb * sg.nx;
    int m0 = mb << 7, n0 = nbk << 7;

    const fp16* B; const float* bias; fp16* O;
    if (nbk < sg.nxK) { B = sg.Bk; bias = sg.bk; O = sg.Ok; }
    else { B = sg.Bv; bias = sg.bv; O = sg.Ov; n0 -= sg.nxK << 7; }

    const fp16* A = sg.A + (size_t)z * sg.aStride + (size_t)m0 * sg.Kdim;
    B += (size_t)n0 * sg.Kdim;
    O += (size_t)z * sg.cStride;
    float scale = sg.scale;

    float c[2][8][4];
#pragma unroll
    for (int mi = 0; mi < 2; mi++)
#pragma unroll
        for (int ni = 0; ni < 8; ni++)
#pragma unroll
            for (int r = 0; r < 4; r++) c[mi][ni][r] = 0.f;

    gemm_main(A, B, sg.Kdim, c, dsm, tid, wm, wn, lid);

#pragma unroll
    for (int mi = 0; mi < 2; mi++) {
#pragma unroll
        for (int ni = 0; ni < 8; ni++) {
            int col = n0 + wn * 64 + ni * 8 + (lid & 3) * 2;
            float bcol0 = bias[col], bcol1 = bias[col + 1];
#pragma unroll
            for (int rh = 0; rh < 2; rh++) {
                int m = m0 + wm * 32 + mi * 16 + (lid >> 2) + rh * 8;
                float v0 = c[mi][ni][rh * 2 + 0];
                float v1 = c[mi][ni][rh * 2 + 1];
                size_t o = (size_t)m * DIM + col;
                *(uint32_t*)&O[o] = pack2(__float2half_rn((v0 + bcol0) * scale),
                                          __float2half_rn((v1 + bcol1) * scale));
            }
        }
    }
}

// ---------------- general GEMM ----------------
// epi: 1: C=res+tanh(g)*(acc+bias) | 2: gelu->fp16 | 3: C=res+tanh(g)*acc
__global__ __launch_bounds__(256) void gemm_mma(
    const fp16* __restrict__ A,
    const fp16* __restrict__ B,
    const float* __restrict__ bias,
    const float* __restrict__ res, const float* __restrict__ gate,
    float* __restrict__ C, fp16* __restrict__ O,
    int N, int K, int epi)
{
    extern __shared__ __align__(128) char dsm[];

    int tid = threadIdx.x, wid = tid >> 5, lid = tid & 31;
    int wm = wid & 3, wn = wid >> 2;
    int m0 = blockIdx.y << 7, n0 = blockIdx.x << 7;

    float c[2][8][4];
#pragma unroll
    for (int mi = 0; mi < 2; mi++)
#pragma unroll
        for (int ni = 0; ni < 8; ni++)
#pragma unroll
            for (int r = 0; r < 4; r++) c[mi][ni][r] = 0.f;

    gemm_main(A + (size_t)m0 * K, B + (size_t)n0 * K, K, c, dsm, tid, wm, wn, lid);

    float gv = (epi == 1 || epi == 3) ? tanhf(*gate) : 0.f;
#pragma unroll
    for (int mi = 0; mi < 2; mi++) {
#pragma unroll
        for (int ni = 0; ni < 8; ni++) {
            int col = n0 + wn * 64 + ni * 8 + (lid & 3) * 2;
            float bcol0 = 0.f, bcol1 = 0.f;
            if (epi == 1) { bcol0 = bias[col]; bcol1 = bias[col + 1]; }
#pragma unroll
            for (int rh = 0; rh < 2; rh++) {
                int m = m0 + wm * 32 + mi * 16 + (lid >> 2) + rh * 8;
                float v0 = c[mi][ni][rh * 2 + 0];
                float v1 = c[mi][ni][rh * 2 + 1];
                size_t o = (size_t)m * N + col;
                if (epi == 1) {
                    C[o]     = res[o]     + gv * (v0 + bcol0);
                    C[o + 1] = res[o + 1] + gv * (v1 + bcol1);
                } else if (epi == 2) {
                    float g0 = 0.5f * v0 * (1.f + erff(v0 * 0.70710678118654752f));
                    float g1 = 0.5f * v1 * (1.f + erff(v1 * 0.70710678118654752f));
                    *(uint32_t*)&O[o] = pack2(__float2half_rn(g0), __float2half_rn(g1));
                } else { // epi == 3
                    C[o]     = res[o]     + gv * v0;
                    C[o + 1] = res[o + 1] + gv * v1;
                }
            }
        }
    }
}

// ---------------- tensor-core flash attention (fp16) ----------------
#define AQ 0
#define AK(st) (17408 + (st) * 8704)
#define AV(st) (34816 + (st) * 8704)
#define AMSK_BYTES 104448
#define ATT_SMEM (AMSK_BYTES + 512)
#define NKT (SKV / 64)

__global__ __launch_bounds__(256) void attn_tc(
    const fp16* __restrict__ qv, const fp16* __restrict__ kk, const fp16* __restrict__ vv,
    const float* __restrict__ qmask, const float* __restrict__ pmask,
    const float* __restrict__ smask, const float* __restrict__ mmask,
    fp16* __restrict__ co)
{
    extern __shared__ __align__(128) char dsm[];
    uint32_t sb = smem_u32(dsm);

    int b = blockIdx.z, h = blockIdx.y, q0 = blockIdx.x * 128;
    int tid = threadIdx.x, wid = tid >> 5, lid = tid & 31;
    int wr = wid * 16;

#pragma unroll
    for (int j = 0; j < 8; j++) {
        int rem = tid + j * 256;
        int r = rem >> 4, cch = rem & 15;
        CP16(sb + (uint32_t)(AQ + r * 136 + cch * 8) * 2,
             qv + (size_t)(b * SQL + q0 + r) * DIM + h * HD + cch * 8);
    }

    auto load_stage = [&](int kt, int st) {
#pragma unroll
        for (int grp = 0; grp < 2; grp++) {
            const fp16* base = grp ? vv : kk;
            uint32_t ab = grp ? (uint32_t)AV(st) : (uint32_t)AK(st);
#pragma unroll
            for (int j = 0; j < 4; j++) {
                int rem = tid + j * 256;
                int r = rem >> 4, cch = rem & 15;
                CP16(sb + (ab + (uint32_t)(r * 136 + cch * 8)) * 2,
                     base + (size_t)(b * SKV + kt + r) * DIM + h * HD + cch * 8);
            }
        }
        if (tid < 64) {
            int kidx = kt + tid;
            const float* srcm;
            if (kidx < SP)           srcm = pmask + b * SP + kidx;
            else if (kidx < SP + SS) srcm = smask + b * SS + (kidx - SP);
            else                     srcm = mmask + b * SMm + (kidx - SP - SS);
            CP4(sb + AMSK_BYTES + st * 256 + tid * 4, srcm);
        }
    };

    float qm2[2];
    qm2[0] = qmask[b * SQL + q0 + wr + (lid >> 2)];
    qm2[1] = qmask[b * SQL + q0 + wr + (lid >> 2) + 8];

    float m2[2] = { -1e30f, -1e30f }, l2[2] = { 0.f, 0.f };
    float o[16][4];
#pragma unroll
    for (int ni = 0; ni < 16; ni++)
#pragma unroll
        for (int r = 0; r < 4; r++) o[ni][r] = 0.f;

    load_stage(0, 0);
    CP_COMMIT();

    for (int t = 0; t < NKT; t++) {
        int st = t & 1;
        CP_WAIT(0);
        __syncthreads();
        if (t + 1 < NKT) { load_stage((t + 1) * 64, st ^ 1); CP_COMMIT(); }

        float cs[8][4];
#pragma unroll
        for (int ni = 0; ni < 8; ni++)
#pragma unroll
            for (int r = 0; r < 4; r++) cs[ni][r] = 0.f;

        uint32_t akb = sb + (uint32_t)AK(st) * 2;
#pragma unroll
        for (int ko = 0; ko < 8; ko++) {
            uint32_t aoff = (uint32_t)((wr + (lid & 15)) * 136 + ko * 16 + ((lid >> 4) << 3)) * 2;
            uint32_t aq[4];
            ldmx4(aq, sb + AQ * 2 + aoff);
#pragma unroll
            for (int p = 0; p < 4; p++) {
                uint32_t brow = (uint32_t)(p * 16 + (lid & 7) + ((lid >> 4) << 3));
                uint32_t boff = (brow * 136 + ko * 16 + (((lid >> 3) & 1) << 3)) * 2;
                uint32_t b4[4];
                ldmx4(b4, akb + boff);
#pragma unroll
                for (int half = 0; half < 2; half++)
                    mma_f16(cs[p * 2 + half], aq, &b4[half * 2]);
            }
        }

        const float* kmf = (const float*)(dsm + AMSK_BYTES + st * 256);
#pragma unroll
        for (int ni = 0; ni < 8; ni++) {
            int c0 = ni * 8 + (lid & 3) * 2;
            float km0 = kmf[c0], km1 = kmf[c0 + 1];
            if (qm2[0] == 0.f || km0 == 0.f) cs[ni][0] = -1e30f;
            if (qm2[0] == 0.f || km1 == 0.f) cs[ni][1] = -1e30f;
            if (qm2[1] == 0.f || km0 == 0.f) cs[ni][2] = -1e30f;
            if (qm2[1] == 0.f || km1 == 0.f) cs[ni][3] = -1e30f;
        }
#pragma unroll
        for (int rh = 0; rh < 2; rh++) {
            float mt = -1e30f;
#pragma unroll
            for (int ni = 0; ni < 8; ni++)
                mt = fmaxf(mt, fmaxf(cs[ni][rh * 2], cs[ni][rh * 2 + 1]));
            mt = fmaxf(mt, __shfl_xor_sync(0xffffffffu, mt, 1));
            mt = fmaxf(mt, __shfl_xor_sync(0xffffffffu, mt, 2));
            float nm = fmaxf(m2[rh], mt);
            float al = __expf(m2[rh] - nm);
            float ps = 0.f;
#pragma unroll
            for (int ni = 0; ni < 8; ni++) {
                float p0 = __expf(cs[ni][rh * 2] - nm);
                float p1 = __expf(cs[ni][rh * 2 + 1] - nm);
                cs[ni][rh * 2] = p0; cs[ni][rh * 2 + 1] = p1;
                ps += p0 + p1;
            }
            ps += __shfl_xor_sync(0xffffffffu, ps, 1);
            ps += __shfl_xor_sync(0xffffffffu, ps, 2);
            l2[rh] = l2[rh] * al + ps;
            m2[rh] = nm;
#pragma unroll
            for (int ni = 0; ni < 16; ni++) {
                o[ni][rh * 2] *= al; o[ni][rh * 2 + 1] *= al;
            }
        }

        uint32_t avb = sb + (uint32_t)AV(st) * 2;
#pragma unroll
        for (int kchunk = 0; kchunk < 4; kchunk++) {
            int t0 = 2 * kchunk, t1 = 2 * kchunk + 1;
            uint32_t pa[4];
            pa[0] = pack2(__float2half_rn(cs[t0][0]), __float2half_rn(cs[t0][1]));
            pa[1] = pack2(__float2half_rn(cs[t0][2]), __float2half_rn(cs[t0][3]));
            pa[2] = pack2(__float2half_rn(cs[t1][0]), __float2half_rn(cs[t1][1]));
            pa[3] = pack2(__float2half_rn(cs[t1][2]), __float2half_rn(cs[t1][3]));
#pragma unroll
            for (int p = 0; p < 8; p++) {
                uint32_t kv = (uint32_t)(kchunk * 16 + ((lid >> 3) & 1) * 8 + (lid & 7));
                uint32_t d  = (uint32_t)(p * 16 + (((lid >> 4) & 1) << 3));
                uint32_t off = (kv * 136 + d) * 2;
                uint32_t bv4[4];
                ldmx4t(bv4, avb + off);
#pragma unroll
                for (int half = 0; half < 2; half++)
                    mma_f16(o[p * 2 + half], pa, &bv4[half * 2]);
            }
        }
    }

#pragma unroll
    for (int rh = 0; rh < 2; rh++) {
        float inv = 1.f / l2[rh];
        int row = q0 + wr + (lid >> 2) + rh * 8;
#pragma unroll
        for (int ni = 0; ni < 16; ni++) {
            int col = h * HD + ni * 8 + (lid & 3) * 2;
            size_t off = (size_t)(b * SQL + row) * DIM + col;
            *(uint32_t*)&co[off] = pack2(__float2half_rn(o[ni][rh * 2] * inv),
                                         __float2half_rn(o[ni][rh * 2 + 1] * inv));
        }
    }
}

// ---------------- launch ----------------
extern "C" void kernel_launch(void* const* d_in, const int* in_sizes, int n_in,
                              void* d_out, int out_size)
{
    const float* x   = (const float*)d_in[0];
    const float* pkv = (const float*)d_in[1];
    const float* skv = (const float*)d_in[2];
    const float* mkv = (const float*)d_in[3];
    const float* qm  = (const float*)d_in[4];
    const float* pm  = (const float*)d_in[5];
    const float* smk = (const float*)d_in[6];
    const float* mmk = (const float*)d_in[7];
    const float* rw  = (const float*)d_in[8];
    const float* Wq  = (const float*)d_in[9];
    const float* bq  = (const float*)d_in[10];
    const float* Wkp = (const float*)d_in[11];
    const float* bkp = (const float*)d_in[12];
    const float* Wvp = (const float*)d_in[13];
    const float* bvp = (const float*)d_in[14];
    const float* Wks = (const float*)d_in[15];
    const float* bks = (const float*)d_in[16];
    const float* Wvs = (const float*)d_in[17];
    const float* bvs = (const float*)d_in[18];
    const float* Wkm = (const float*)d_in[19];
    const float* bkm = (const float*)d_in[20];
    const float* Wvm = (const float*)d_in[21];
    const float* bvm = (const float*)d_in[22];
    const float* Wo  = (const float*)d_in[23];
    const float* bo  = (const float*)d_in[24];
    const float* lg  = (const float*)d_in[25];
    const float* lb  = (const float*)d_in[26];
    const float* W1  = (const float*)d_in[27];
    const float* W2  = (const float*)d_in[28];
    const float* ga  = (const float*)d_in[29];
    const float* gf  = (const float*)d_in[30];
    float* out = (float*)d_out;

    float* hb;
    cudaGetSymbolAddress((void**)&hb, g_h);

    fp16 *xn, *pk, *sk, *mk, *ct, *ln, *md, *qv, *k1, *v1;
    cudaGetSymbolAddress((void**)&xn, g_xn);
    cudaGetSymbolAddress((void**)&pk, g_pk);
    cudaGetSymbolAddress((void**)&sk, g_sk);
    cudaGetSymbolAddress((void**)&mk, g_mk);
    cudaGetSymbolAddress((void**)&ct, g_ct);
    cudaGetSymbolAddress((void**)&ln, g_ln);
    cudaGetSymbolAddress((void**)&md, g_md);
    cudaGetSymbolAddress((void**)&qv, g_q);
    cudaGetSymbolAddress((void**)&k1, g_k1);
    cudaGetSymbolAddress((void**)&v1, g_v1);

    fp16 *wq, *kp, *vp, *ks, *vs, *km, *vm, *wo, *w1, *w2;
    cudaGetSymbolAddress((void**)&wq, g_wq);
    cudaGetSymbolAddress((void**)&kp, g_kp); cudaGetSymbolAddress((void**)&vp, g_vp);
    cudaGetSymbolAddress((void**)&ks, g_ks); cudaGetSymbolAddress((void**)&vs, g_vs);
    cudaGetSymbolAddress((void**)&km, g_km); cudaGetSymbolAddress((void**)&vm, g_vm);
    cudaGetSymbolAddress((void**)&wo, g_wo);
    cudaGetSymbolAddress((void**)&w1, g_w1); cudaGetSymbolAddress((void**)&w2, g_w2);

    size_t gemm_sh = NSTG * STGB;   // 80 KB
    cudaFuncSetAttribute(gemm_mma,  cudaFuncAttributeMaxDynamicSharedMemorySize, (int)gemm_sh);
    cudaFuncSetAttribute(gemm_proj, cudaFuncAttributeMaxDynamicSharedMemorySize, (int)gemm_sh);
    cudaFuncSetAttribute(attn_tc,   cudaFuncAttributeMaxDynamicSharedMemorySize, ATT_SMEM);

    // ---- prep (3 launches) ----
    rms_cvt_kernel<<<BN * SQL, 256>>>(x, rw, xn);

    int c0 = (BN * SP * DP) / 1024;
    int c1 = c0 + (BN * SS * DS) / 1024;
    int c2 = c1 + (BN * SMm * DMm) / 1024;
    cvt_all<<<c2, 256>>>(pkv, pk, c0, skv, sk, c1, mkv, mk, c2);

    WTab tab;
    {
        const float* Ws[10] = { Wq, Wkp, Wvp, Wks, Wvs, Wkm, Wvm, Wo, W1, W2 };
        fp16* Os[10]        = { wq, kp,  vp,  ks,  vs,  km,  vm,  wo, w1, w2 };
        int Kk[10] = { DIM, DP, DP, DS, DS, DMm, DMm, DIM, DIM, INNER };
        int Nn[10] = { DIM, DIM, DIM, DIM, DIM, DIM, DIM, DIM, INNER, DIM };
        int cum = 0;
        for (int i = 0; i < 10; i++) {
            tab.e[i].W = Ws[i]; tab.e[i].O = Os[i];
            tab.e[i].K = Kk[i]; tab.e[i].N = Nn[i];
            tab.e[i].cum = cum;
            cum += (Nn[i] / 32) * (Kk[i] / 32);
        }
        tcvt_all<<<cum, 256>>>(tab);
    }

    // ---- #4: ALL projections in one launch (Q + 3x merged K|V) ----
    PTab pt;
    // seg0: Q  (256 blocks)
    pt.e[0] = { xn, wq, wq, bq, bq, qv, qv, 0, 0, DIM, 16, 16, 16, 0, 0.25f };
    // seg1: protein K|V (512 blocks)
    pt.e[1] = { pk, kp, vp, bkp, bvp, k1, v1,
                (long)SP * DP, (long)SKV * DIM, DP, 32, 16, 8, 256, 1.f };
    // seg2: structure K|V (512 blocks)
    pt.e[2] = { sk, ks, vs, bks, bvs, k1 + (size_t)SP * DIM, v1 + (size_t)SP * DIM,
                (long)SS * DS, (long)SKV * DIM, DS, 32, 16, 8, 768, 1.f };
    // seg3: msa K|V (256 blocks)
    pt.e[3] = { mk, km, vm, bkm, bvm,
                k1 + (size_t)(SP + SS) * DIM, v1 + (size_t)(SP + SS) * DIM,
                (long)SMm * DMm, (long)SKV * DIM, DMm, 32, 16, 4, 1280, 1.f };
    gemm_proj<<<1536, 256, gemm_sh>>>(pt);

    // #5: flash attention -> fp16 ctx
    attn_tc<<<dim3(SQL / 128, NH, BN), 256, ATT_SMEM>>>(qv, k1, v1,
                                                        qm, pm, smk, mmk, ct);

    // #6: Wo projection + gated residual
    gemm_mma<<<dim3(DIM / 128, 16, 1), 256, gemm_sh>>>(
        ct, wo, bo, x, ga, hb, nullptr, DIM, DIM, 1);

    // #7: LayerNorm -> fp16
    ln_cvt_kernel<<<BN * SQL, 256>>>(hb, lg, lb, ln);

    // #8: FFW up + GELU -> fp16
    gemm_mma<<<dim3(INNER / 128, 16, 1), 256, gemm_sh>>>(
        ln, w1, nullptr, nullptr, nullptr, nullptr, md, INNER, DIM, 2);

    // #9: FFW down + gated residual -> out
    gemm_mma<<<dim3(DIM / 128, 16, 1), 256, gemm_sh>>>(
        md, w2, nullptr, hb, gf, out, nullptr, DIM, INNER, 3);
}